// round 3
// baseline (speedup 1.0000x reference)
#include <cuda_runtime.h>
#include <cuda_bf16.h>
#include <mma.h>

using namespace nvcuda;

#define BATCH 32
#define SEQ   2048
#define BL    (BATCH*SEQ)   // 65536 rows
#define DD    768
#define HH    512
#define EPSF  1e-5f

// ---------------------------------------------------------------------------
// Static scratch (compile-time device globals: allowed; runtime allocs: not)
// ---------------------------------------------------------------------------
__device__ __nv_bfloat16 g_hbf[(size_t)BL * HH];  // 64 MB post-GEMM1 activations
__device__ float g_sum[HH];
__device__ float g_sumsq[HH];
__device__ float g_mean[HH];
__device__ float g_rstdg[HH];      // rsqrt(var+eps)*gamma
__device__ float g_counts[BATCH];
__device__ float g_nvalid;
__device__ float g_pool[BATCH * HH];

// ---------------------------------------------------------------------------
// cp.async helpers
// ---------------------------------------------------------------------------
__device__ __forceinline__ unsigned smem_u32(const void* p) {
    return (unsigned)__cvta_generic_to_shared(p);
}
#define CP_ASYNC16(sa, ga) \
    asm volatile("cp.async.cg.shared.global [%0], [%1], 16;\n" :: "r"(sa), "l"(ga))
#define CP_COMMIT() asm volatile("cp.async.commit_group;\n" ::)
#define CP_WAIT(n)  asm volatile("cp.async.wait_group %0;\n" :: "n"(n))

// ---------------------------------------------------------------------------
// Zero accumulators (every replay; graph-captured)
// ---------------------------------------------------------------------------
__global__ void k_init() {
    int i = blockIdx.x * blockDim.x + threadIdx.x;
    if (i < HH) { g_sum[i] = 0.f; g_sumsq[i] = 0.f; }
    if (i < BATCH * HH) g_pool[i] = 0.f;
    if (i == 0) g_nvalid = 0.f;
}

// ---------------------------------------------------------------------------
// Per-batch valid-token counts + total
// ---------------------------------------------------------------------------
__global__ void k_counts(const int* __restrict__ mask) {
    __shared__ int sh[256];
    int b = blockIdx.x, t = threadIdx.x;
    int s = 0;
    for (int l = t; l < SEQ; l += 256) s += mask[b * SEQ + l];
    sh[t] = s;
    __syncthreads();
    for (int o = 128; o > 0; o >>= 1) {
        if (t < o) sh[t] += sh[t + o];
        __syncthreads();
    }
    if (t == 0) {
        g_counts[b] = fmaxf((float)sh[0], 1.f);
        atomicAdd(&g_nvalid, (float)sh[0]);
    }
}

// ---------------------------------------------------------------------------
// GEMM1: h = hidden[65536,768] @ W1[768,512], tf32 wmma, cp.async 2-stage,
// fused epilogue: bf16 h store + masked per-channel sum/sumsq.
// b1 omitted (batchnorm mean-subtraction cancels per-channel constants).
// ---------------------------------------------------------------------------
#define G1_BM 128
#define G1_BN 128
#define G1_BK 32
#define A_LD  36     // 32 + 4 pad
#define B_LD  132    // 128 + 4 pad
#define A_STG (G1_BM * A_LD)   // floats per A stage
#define B_STG (G1_BK * B_LD)   // floats per B stage
#define PIPE_FLOATS (2 * A_STG + 2 * B_STG)
#define TILE_LD 132
#define SMEM_BYTES (PIPE_FLOATS * 4)   // 70656 B (>= epilogue's 69120 B)

__global__ void __launch_bounds__(256) k_gemm1(const float* __restrict__ A,
                                               const float* __restrict__ B,
                                               const int* __restrict__ mask) {
    extern __shared__ float sm[];
    float* As = sm;                  // [2][128][A_LD]
    float* Bs = sm + 2 * A_STG;      // [2][32][B_LD]

    const int bm = blockIdx.y * G1_BM;
    const int bn = blockIdx.x * G1_BN;
    const int t = threadIdx.x;
    const int warp = t >> 5;
    const int wm = (warp >> 2) * 64;
    const int wn = (warp & 3) * 32;

    wmma::fragment<wmma::accumulator, 16, 16, 8, float> acc[4][2];
#pragma unroll
    for (int i = 0; i < 4; i++)
#pragma unroll
        for (int j = 0; j < 2; j++) wmma::fill_fragment(acc[i][j], 0.f);

    auto loadStage = [&](int it) {
        const int k0 = it * G1_BK;
        const int s = it & 1;
        float* as = As + s * A_STG;
        float* bs = Bs + s * B_STG;
        // A tile: 128 rows x 32 floats = 1024 16B-chunks
#pragma unroll
        for (int j = 0; j < 4; j++) {
            int i = j * 256 + t;
            int r = i >> 3, c = (i & 7) * 4;
            CP_ASYNC16(smem_u32(as + r * A_LD + c),
                       A + (size_t)(bm + r) * DD + k0 + c);
        }
        // B tile: 32 rows x 128 floats = 1024 chunks
#pragma unroll
        for (int j = 0; j < 4; j++) {
            int i = j * 256 + t;
            int r = i >> 5, c = (i & 31) * 4;
            CP_ASYNC16(smem_u32(bs + r * B_LD + c),
                       B + (size_t)(k0 + r) * HH + bn + c);
        }
        CP_COMMIT();
    };

    loadStage(0);
    const int NIT = DD / G1_BK;   // 24
    for (int it = 0; it < NIT; it++) {
        if (it + 1 < NIT) {
            loadStage(it + 1);
            CP_WAIT(1);
        } else {
            CP_WAIT(0);
        }
        __syncthreads();
        const int s = it & 1;
        const float* as = As + s * A_STG;
        const float* bs = Bs + s * B_STG;
#pragma unroll
        for (int kk = 0; kk < G1_BK; kk += 8) {
            wmma::fragment<wmma::matrix_a, 16, 16, 8, wmma::precision::tf32, wmma::row_major> fa[4];
            wmma::fragment<wmma::matrix_b, 16, 16, 8, wmma::precision::tf32, wmma::row_major> fb[2];
#pragma unroll
            for (int i = 0; i < 4; i++)
                wmma::load_matrix_sync(fa[i], as + (wm + i * 16) * A_LD + kk, A_LD);
#pragma unroll
            for (int j = 0; j < 2; j++)
                wmma::load_matrix_sync(fb[j], bs + kk * B_LD + wn + j * 16, B_LD);
#pragma unroll
            for (int i = 0; i < 4; i++)
#pragma unroll
                for (int j = 0; j < 2; j++)
                    wmma::mma_sync(acc[i][j], fa[i], fb[j], acc[i][j]);
        }
        __syncthreads();
    }

    // ---- Epilogue: stage tile in smem (aliases pipeline buffers) ----
    float* tile = sm;                       // [128][TILE_LD]
    float* cs = sm + G1_BM * TILE_LD;       // [128]
    float* cq = cs + G1_BM;                 // [128]
    int*   mk = (int*)(cq + G1_BM);         // [128]

#pragma unroll
    for (int i = 0; i < 4; i++)
#pragma unroll
        for (int j = 0; j < 2; j++)
            wmma::store_matrix_sync(tile + (wm + i * 16) * TILE_LD + wn + j * 16,
                                    acc[i][j], TILE_LD, wmma::mem_row_major);
    if (t < 128) mk[t] = mask[bm + t];
    __syncthreads();

    // bf16 h store (vectorized bf16x2)
    __nv_bfloat162* H2 = (__nv_bfloat162*)g_hbf;
#pragma unroll
    for (int i = t; i < G1_BM * 64; i += 256) {
        int r = i >> 6, c2 = (i & 63);
        float x = tile[r * TILE_LD + 2 * c2];
        float y = tile[r * TILE_LD + 2 * c2 + 1];
        H2[((size_t)(bm + r) * HH + bn) / 2 + c2] = __floats2bfloat162_rn(x, y);
    }

    // masked per-channel sum / sumsq (two half-column partials)
    int col = t & 127, half = t >> 7;
    float s = 0.f, q = 0.f;
    int rbeg = half * 64;
#pragma unroll 4
    for (int r = rbeg; r < rbeg + 64; r++) {
        if (mk[r]) {
            float v = tile[r * TILE_LD + col];
            s += v;
            q += v * v;
        }
    }
    if (half == 0) { cs[col] = s; cq[col] = q; }
    __syncthreads();
    if (half == 1) { cs[col] += s; cq[col] += q; }
    __syncthreads();
    if (t < 128) {
        atomicAdd(&g_sum[bn + t], cs[t]);
        atomicAdd(&g_sumsq[bn + t], cq[t]);
    }
}

// ---------------------------------------------------------------------------
__global__ void k_finalize(const float* __restrict__ gamma) {
    int c = threadIdx.x;
    float n = fmaxf(g_nvalid, 1.f);
    float mean = g_sum[c] / n;
    float var = g_sumsq[c] / n - mean * mean;
    g_mean[c] = mean;
    g_rstdg[c] = rsqrtf(fmaxf(var, 0.f) + EPSF) * gamma[c];
}

// ---------------------------------------------------------------------------
// Normalize + ReLU + masked pool, reading bf16 h
// ---------------------------------------------------------------------------
__global__ void k_pool(const int* __restrict__ mask, const float* __restrict__ beta) {
    int b = blockIdx.x, c = threadIdx.x;
    int l0 = blockIdx.y * 256;
    float mean = g_mean[c], rs = g_rstdg[c], be = beta[c];
    float s = 0.f;
    const size_t base = (size_t)(b * SEQ + l0) * HH;
    const int* mrow = mask + b * SEQ + l0;
#pragma unroll 4
    for (int l = 0; l < 256; l++) {
        if (mrow[l]) {
            float v = __bfloat162float(g_hbf[base + (size_t)l * HH + c]);
            v = (v - mean) * rs + be;
            s += fmaxf(v, 0.f);
        }
    }
    atomicAdd(&g_pool[b * HH + c], s);
}

// ---------------------------------------------------------------------------
// Tiny GEMM2 on pooled features
// ---------------------------------------------------------------------------
__global__ void k_gemm2(const float* __restrict__ W2, const float* __restrict__ b2,
                        float* __restrict__ out) {
    __shared__ float ph[HH];
    int b = blockIdx.x, k = threadIdx.x;
    ph[k] = g_pool[b * HH + k] / g_counts[b];
    __syncthreads();
    float acc = b2[k];
#pragma unroll 8
    for (int c = 0; c < HH; c++) acc += ph[c] * W2[c * HH + k];
    out[b * HH + k] = acc;
}

// ---------------------------------------------------------------------------
extern "C" void kernel_launch(void* const* d_in, const int* in_sizes, int n_in,
                              void* d_out, int out_size) {
    const float* hidden = (const float*)d_in[0];
    const int*   mask   = (const int*)d_in[1];
    const float* W1     = (const float*)d_in[2];
    // d_in[3] = b1: cancelled by batch-norm mean subtraction
    const float* gamma  = (const float*)d_in[4];
    const float* beta   = (const float*)d_in[5];
    const float* W2     = (const float*)d_in[6];
    const float* b2     = (const float*)d_in[7];
    float* out = (float*)d_out;

    // Unconditional every call (no static guards — harness contract).
    cudaFuncSetAttribute(k_gemm1, cudaFuncAttributeMaxDynamicSharedMemorySize,
                         SMEM_BYTES);

    k_init<<<64, 256>>>();
    k_counts<<<BATCH, 256>>>(mask);
    k_gemm1<<<dim3(HH / G1_BN, BL / G1_BM), 256, SMEM_BYTES>>>(hidden, W1, mask);
    k_finalize<<<1, HH>>>(gamma);
    k_pool<<<dim3(BATCH, SEQ / 256), HH>>>(mask, beta);
    k_gemm2<<<BATCH, HH>>>(W2, b2, out);
}

// round 6
// speedup vs baseline: 2.0688x; 2.0688x over previous
#include <cuda_runtime.h>
#include <cuda_bf16.h>
#include <mma.h>
#include <cstdint>

using namespace nvcuda;

#define BATCH 32
#define SEQ   2048
#define BL    65536
#define DD    768
#define HH    512
#define EPSF  1e-5f

// ---------------------------------------------------------------------------
// Static scratch
// ---------------------------------------------------------------------------
__device__ __nv_bfloat16 g_abf[(size_t)BL * DD];   // 96 MB: hidden in bf16
__device__ __nv_bfloat16 g_w1bf[DD * HH];          // W1 in bf16, [768][512]
__device__ __nv_bfloat16 g_hbf[(size_t)BL * HH];   // 64 MB: activations
__device__ float g_sum[HH];
__device__ float g_sumsq[HH];
__device__ float g_cnt[BATCH];
__device__ float g_pool[BATCH * HH];

// ---------------------------------------------------------------------------
// cp.async helpers (sm_80 — safe on plain sm_103 target)
// ---------------------------------------------------------------------------
__device__ __forceinline__ unsigned smem_u32(const void* p) {
    return (unsigned)__cvta_generic_to_shared(p);
}
#define CP_ASYNC16(sa, ga) \
    asm volatile("cp.async.cg.shared.global [%0], [%1], 16;\n" :: "r"(sa), "l"(ga))
#define CP_COMMIT() asm volatile("cp.async.commit_group;\n" ::)
#define CP_WAIT(n)  asm volatile("cp.async.wait_group %0;\n" :: "n"(n))

// ---------------------------------------------------------------------------
// k_pre: A & W1 -> bf16, per-batch counts, zero accumulators
// ---------------------------------------------------------------------------
#define PRE_A_BLK 6144    // 12,582,912 float4 of A / 2048 per block
#define PRE_W_BLK 48      // 98,304 float4 of W1
__global__ void k_pre(const float* __restrict__ A, const float* __restrict__ W1,
                      const int* __restrict__ mask) {
    int blk = blockIdx.x, t = threadIdx.x;
    if (blk < PRE_A_BLK) {
        const float4* src = (const float4*)A;
        uint2* dst = (uint2*)g_abf;
#pragma unroll
        for (int j = 0; j < 8; j++) {
            int idx = blk * 2048 + j * 256 + t;
            float4 v = src[idx];
            __nv_bfloat162 p0 = __floats2bfloat162_rn(v.x, v.y);
            __nv_bfloat162 p1 = __floats2bfloat162_rn(v.z, v.w);
            dst[idx] = make_uint2(*(uint32_t*)&p0, *(uint32_t*)&p1);
        }
    } else if (blk < PRE_A_BLK + PRE_W_BLK) {
        int b = blk - PRE_A_BLK;
        const float4* src = (const float4*)W1;
        uint2* dst = (uint2*)g_w1bf;
#pragma unroll
        for (int j = 0; j < 8; j++) {
            int idx = b * 2048 + j * 256 + t;
            float4 v = src[idx];
            __nv_bfloat162 p0 = __floats2bfloat162_rn(v.x, v.y);
            __nv_bfloat162 p1 = __floats2bfloat162_rn(v.z, v.w);
            dst[idx] = make_uint2(*(uint32_t*)&p0, *(uint32_t*)&p1);
        }
    } else if (blk < PRE_A_BLK + PRE_W_BLK + BATCH) {
        __shared__ int sh[256];
        int b = blk - PRE_A_BLK - PRE_W_BLK;
        int s = 0;
        for (int l = t; l < SEQ; l += 256) s += mask[b * SEQ + l];
        sh[t] = s;
        __syncthreads();
        for (int o = 128; o > 0; o >>= 1) {
            if (t < o) sh[t] += sh[t + o];
            __syncthreads();
        }
        if (t == 0) g_cnt[b] = (float)sh[0];
    } else {
        int b = blk - PRE_A_BLK - PRE_W_BLK - BATCH;   // 0..64
        if (b < 64) {
            g_pool[b * 256 + t] = 0.f;
        } else {
            g_sum[t] = 0.f; g_sum[t + 256] = 0.f;
            g_sumsq[t] = 0.f; g_sumsq[t + 256] = 0.f;
        }
    }
}
#define PRE_BLOCKS (PRE_A_BLK + PRE_W_BLK + BATCH + 65)

// ---------------------------------------------------------------------------
// GEMM1: h = A[65536,768] @ W1[768,512], bf16 wmma (LDSM path), fp32 accum,
// 4-stage cp.async. Fused epilogue: bf16 h store + masked per-channel stats.
// b1 omitted (batchnorm mean-subtraction cancels per-channel constants).
// ---------------------------------------------------------------------------
#define BM 128
#define BN 128
#define BK 32
#define STAGES 4
#define A_LD 40    // bf16 elements: 32 + 8 pad (16B)
#define B_LD 136   // 128 + 8 pad
#define A_STG (BM * A_LD)           // bf16 per A stage (10240 B)
#define B_STG (BK * B_LD)           // bf16 per B stage (8704 B)
#define STG_BF (A_STG + B_STG)
#define SMEM_BYTES (STAGES * STG_BF * 2)   // 75776 B
#define TILE_LD 132                         // epilogue fp32 tile stride

__global__ void __launch_bounds__(256, 1) k_gemm1(const int* __restrict__ mask) {
    extern __shared__ __nv_bfloat16 sm[];

    const int bn = blockIdx.x * BN;
    const int bm = blockIdx.y * BM;
    const int t = threadIdx.x;
    const int warp = t >> 5;
    const int wm = (warp >> 2) * 64;   // 2x4 warp grid: warp tile 64x32
    const int wn = (warp & 3) * 32;

    wmma::fragment<wmma::accumulator, 16, 16, 16, float> acc[4][2];
#pragma unroll
    for (int i = 0; i < 4; i++)
#pragma unroll
        for (int j = 0; j < 2; j++) wmma::fill_fragment(acc[i][j], 0.f);

    auto prefetch = [&](int it) {
        const int k0 = it * BK;
        __nv_bfloat16* st = sm + (it % STAGES) * STG_BF;
        uint32_t as = smem_u32(st);
        uint32_t bs = smem_u32(st + A_STG);
        // A tile: 128 rows x 32 bf16 = 512 16B-chunks
#pragma unroll
        for (int j = 0; j < 2; j++) {
            int c = j * 256 + t;
            int r = c >> 2, cc = (c & 3) * 8;
            CP_ASYNC16(as + (r * A_LD + cc) * 2,
                       g_abf + (size_t)(bm + r) * DD + k0 + cc);
        }
        // B tile: 32 rows x 128 bf16 = 512 chunks
#pragma unroll
        for (int j = 0; j < 2; j++) {
            int c = j * 256 + t;
            int r = c >> 4, cc = (c & 15) * 8;
            CP_ASYNC16(bs + (r * B_LD + cc) * 2,
                       g_w1bf + (size_t)(k0 + r) * HH + bn + cc);
        }
        CP_COMMIT();
    };

    prefetch(0); prefetch(1); prefetch(2);

    const int NIT = DD / BK;   // 24
    for (int it = 0; it < NIT; it++) {
        CP_WAIT(2);            // stage `it` complete
        __syncthreads();       // all warps done with stage it-1 (its buffer now free)
        if (it + 3 < NIT) prefetch(it + 3);
        const __nv_bfloat16* st = sm + (it % STAGES) * STG_BF;
        const __nv_bfloat16* as = st;
        const __nv_bfloat16* bs = st + A_STG;
#pragma unroll
        for (int kk = 0; kk < BK; kk += 16) {
            wmma::fragment<wmma::matrix_a, 16, 16, 16, __nv_bfloat16, wmma::row_major> fa[4];
            wmma::fragment<wmma::matrix_b, 16, 16, 16, __nv_bfloat16, wmma::row_major> fb[2];
#pragma unroll
            for (int i = 0; i < 4; i++)
                wmma::load_matrix_sync(fa[i], as + (wm + i * 16) * A_LD + kk, A_LD);
#pragma unroll
            for (int j = 0; j < 2; j++)
                wmma::load_matrix_sync(fb[j], bs + kk * B_LD + wn + j * 16, B_LD);
#pragma unroll
            for (int i = 0; i < 4; i++)
#pragma unroll
                for (int j = 0; j < 2; j++)
                    wmma::mma_sync(acc[i][j], fa[i], fb[j], acc[i][j]);
        }
    }
    __syncthreads();

    // ---- Epilogue: fp32 tile in smem, bf16 h store + masked stats ----
    float* tile = (float*)sm;                 // [128][TILE_LD]
    float* cs = tile + BM * TILE_LD;          // [128]
    float* cq = cs + BM;                      // [128]
    int*   mk = (int*)(cq + BM);              // [128]

#pragma unroll
    for (int i = 0; i < 4; i++)
#pragma unroll
        for (int j = 0; j < 2; j++)
            wmma::store_matrix_sync(tile + (wm + i * 16) * TILE_LD + wn + j * 16,
                                    acc[i][j], TILE_LD, wmma::mem_row_major);
    if (t < 128) mk[t] = mask[bm + t];
    __syncthreads();

    // bf16 h store (bf16x2 vectorized)
    __nv_bfloat162* H2 = (__nv_bfloat162*)g_hbf;
#pragma unroll
    for (int i = t; i < BM * 64; i += 256) {
        int r = i >> 6, c2 = (i & 63);
        float x = tile[r * TILE_LD + 2 * c2];
        float y = tile[r * TILE_LD + 2 * c2 + 1];
        H2[((size_t)(bm + r) * HH + bn) / 2 + c2] = __floats2bfloat162_rn(x, y);
    }

    // masked per-channel sum / sumsq (two half-column partials)
    int col = t & 127, half = t >> 7;
    float s = 0.f, q = 0.f;
    int rbeg = half * 64;
#pragma unroll 4
    for (int r = rbeg; r < rbeg + 64; r++) {
        if (mk[r]) {
            float v = tile[r * TILE_LD + col];
            s += v;
            q += v * v;
        }
    }
    if (half == 0) { cs[col] = s; cq[col] = q; }
    __syncthreads();
    if (half == 1) { cs[col] += s; cq[col] += q; }
    __syncthreads();
    if (t < 128) {
        atomicAdd(&g_sum[bn + t], cs[t]);
        atomicAdd(&g_sumsq[bn + t], cq[t]);
    }
}

// ---------------------------------------------------------------------------
// Pool: fused finalize + normalize + ReLU + masked sum (bf16 h read)
// ---------------------------------------------------------------------------
__global__ void k_pool(const int* __restrict__ mask, const float* __restrict__ gamma,
                       const float* __restrict__ beta) {
    int b = blockIdx.x, c = threadIdx.x, l0 = blockIdx.y * 256;
    float n = 0.f;
#pragma unroll
    for (int i = 0; i < BATCH; i++) n += g_cnt[i];
    n = fmaxf(n, 1.f);
    float mean = g_sum[c] / n;
    float var = g_sumsq[c] / n - mean * mean;
    float rs = rsqrtf(fmaxf(var, 0.f) + EPSF) * gamma[c];
    float be = beta[c];
    float s = 0.f;
    const size_t base = (size_t)(b * SEQ + l0) * HH;
    const int* mrow = mask + b * SEQ + l0;
#pragma unroll 4
    for (int l = 0; l < 256; l++) {
        if (mrow[l]) {
            float v = __bfloat162float(g_hbf[base + (size_t)l * HH + c]);
            s += fmaxf((v - mean) * rs + be, 0.f);
        }
    }
    atomicAdd(&g_pool[b * HH + c], s);
}

// ---------------------------------------------------------------------------
// Tiny GEMM2 on pooled features
// ---------------------------------------------------------------------------
__global__ void k_gemm2(const float* __restrict__ W2, const float* __restrict__ b2,
                        float* __restrict__ out) {
    __shared__ float ph[HH];
    int b = blockIdx.x, k = threadIdx.x;
    ph[k] = g_pool[b * HH + k] / fmaxf(g_cnt[b], 1.f);
    __syncthreads();
    float acc = b2[k];
#pragma unroll 8
    for (int c = 0; c < HH; c++) acc += ph[c] * W2[c * HH + k];
    out[b * HH + k] = acc;
}

// ---------------------------------------------------------------------------
extern "C" void kernel_launch(void* const* d_in, const int* in_sizes, int n_in,
                              void* d_out, int out_size) {
    const float* hidden = (const float*)d_in[0];
    const int*   mask   = (const int*)d_in[1];
    const float* W1     = (const float*)d_in[2];
    // d_in[3] = b1: cancelled by batch-norm mean subtraction
    const float* gamma  = (const float*)d_in[4];
    const float* beta   = (const float*)d_in[5];
    const float* W2     = (const float*)d_in[6];
    const float* b2     = (const float*)d_in[7];
    float* out = (float*)d_out;

    cudaFuncSetAttribute(k_gemm1, cudaFuncAttributeMaxDynamicSharedMemorySize,
                         SMEM_BYTES);

    k_pre<<<PRE_BLOCKS, 256>>>(hidden, W1, mask);
    k_gemm1<<<dim3(HH / BN, BL / BM), 256, SMEM_BYTES>>>(mask);
    k_pool<<<dim3(BATCH, SEQ / 256), HH>>>(mask, gamma, beta);
    k_gemm2<<<BATCH, HH>>>(W2, b2, out);
}

// round 7
// speedup vs baseline: 2.5837x; 1.2489x over previous
#include <cuda_runtime.h>
#include <cuda_bf16.h>
#include <mma.h>
#include <cstdint>

using namespace nvcuda;

#define BATCH 32
#define SEQ   2048
#define BL    65536
#define DD    768
#define HH    512
#define EPSF  1e-5f

// ---------------------------------------------------------------------------
// Static scratch
// ---------------------------------------------------------------------------
__device__ __nv_bfloat16 g_abf[(size_t)BL * DD];   // 96 MB: hidden in bf16
__device__ __nv_bfloat16 g_w1bf[DD * HH];          // W1 in bf16, [768][512]
__device__ __nv_bfloat16 g_hbf[(size_t)BL * HH];   // 64 MB: activations
__device__ float g_sum[HH];
__device__ float g_sumsq[HH];
__device__ float g_cnt[BATCH];
__device__ float g_pool[BATCH * HH];

// ---------------------------------------------------------------------------
// cp.async helpers
// ---------------------------------------------------------------------------
__device__ __forceinline__ unsigned smem_u32(const void* p) {
    return (unsigned)__cvta_generic_to_shared(p);
}
#define CP_ASYNC16(sa, ga) \
    asm volatile("cp.async.cg.shared.global [%0], [%1], 16;\n" :: "r"(sa), "l"(ga))
#define CP_COMMIT() asm volatile("cp.async.commit_group;\n" ::)
#define CP_WAIT(n)  asm volatile("cp.async.wait_group %0;\n" :: "n"(n))

// ---------------------------------------------------------------------------
// k_pre: A & W1 -> bf16, per-batch counts, zero accumulators
// ---------------------------------------------------------------------------
#define PRE_A_BLK 6144
#define PRE_W_BLK 48
__global__ void k_pre(const float* __restrict__ A, const float* __restrict__ W1,
                      const int* __restrict__ mask) {
    int blk = blockIdx.x, t = threadIdx.x;
    if (blk < PRE_A_BLK) {
        const float4* src = (const float4*)A;
        uint2* dst = (uint2*)g_abf;
#pragma unroll
        for (int j = 0; j < 8; j++) {
            int idx = blk * 2048 + j * 256 + t;
            float4 v = src[idx];
            __nv_bfloat162 p0 = __floats2bfloat162_rn(v.x, v.y);
            __nv_bfloat162 p1 = __floats2bfloat162_rn(v.z, v.w);
            dst[idx] = make_uint2(*(uint32_t*)&p0, *(uint32_t*)&p1);
        }
    } else if (blk < PRE_A_BLK + PRE_W_BLK) {
        int b = blk - PRE_A_BLK;
        const float4* src = (const float4*)W1;
        uint2* dst = (uint2*)g_w1bf;
#pragma unroll
        for (int j = 0; j < 8; j++) {
            int idx = b * 2048 + j * 256 + t;
            float4 v = src[idx];
            __nv_bfloat162 p0 = __floats2bfloat162_rn(v.x, v.y);
            __nv_bfloat162 p1 = __floats2bfloat162_rn(v.z, v.w);
            dst[idx] = make_uint2(*(uint32_t*)&p0, *(uint32_t*)&p1);
        }
    } else if (blk < PRE_A_BLK + PRE_W_BLK + BATCH) {
        __shared__ int sh[256];
        int b = blk - PRE_A_BLK - PRE_W_BLK;
        int s = 0;
        for (int l = t; l < SEQ; l += 256) s += mask[b * SEQ + l];
        sh[t] = s;
        __syncthreads();
        for (int o = 128; o > 0; o >>= 1) {
            if (t < o) sh[t] += sh[t + o];
            __syncthreads();
        }
        if (t == 0) g_cnt[b] = (float)sh[0];
    } else {
        int b = blk - PRE_A_BLK - PRE_W_BLK - BATCH;   // 0..64
        if (b < 64) {
            g_pool[b * 256 + t] = 0.f;
        } else {
            g_sum[t] = 0.f; g_sum[t + 256] = 0.f;
            g_sumsq[t] = 0.f; g_sumsq[t + 256] = 0.f;
        }
    }
}
#define PRE_BLOCKS (PRE_A_BLK + PRE_W_BLK + BATCH + 65)

// ---------------------------------------------------------------------------
// GEMM1: h = A[65536,768] @ W1[768,512], bf16 wmma, fp32 accum,
// 4-stage cp.async, 2 CTAs/SM. Fused epilogue: bf16 h + masked stats.
// ---------------------------------------------------------------------------
#define BM 128
#define BN 128
#define BK 32
#define STAGES 4
#define A_LD 40
#define B_LD 136
#define A_STG (BM * A_LD)
#define B_STG (BK * B_LD)
#define STG_BF (A_STG + B_STG)
#define SMEM_BYTES (STAGES * STG_BF * 2)   // 75776 B (x2 CTAs = 148 KB/SM)
#define TILE_LD 132

__global__ void __launch_bounds__(256, 2) k_gemm1(const int* __restrict__ mask) {
    extern __shared__ __nv_bfloat16 sm[];

    const int bn = blockIdx.x * BN;
    const int bm = blockIdx.y * BM;
    const int t = threadIdx.x;
    const int warp = t >> 5;
    const int wm = (warp >> 2) * 64;
    const int wn = (warp & 3) * 32;

    wmma::fragment<wmma::accumulator, 16, 16, 16, float> acc[4][2];
#pragma unroll
    for (int i = 0; i < 4; i++)
#pragma unroll
        for (int j = 0; j < 2; j++) wmma::fill_fragment(acc[i][j], 0.f);

    auto prefetch = [&](int it) {
        const int k0 = it * BK;
        __nv_bfloat16* st = sm + (it % STAGES) * STG_BF;
        uint32_t as = smem_u32(st);
        uint32_t bs = smem_u32(st + A_STG);
#pragma unroll
        for (int j = 0; j < 2; j++) {
            int c = j * 256 + t;
            int r = c >> 2, cc = (c & 3) * 8;
            CP_ASYNC16(as + (r * A_LD + cc) * 2,
                       g_abf + (size_t)(bm + r) * DD + k0 + cc);
        }
#pragma unroll
        for (int j = 0; j < 2; j++) {
            int c = j * 256 + t;
            int r = c >> 4, cc = (c & 15) * 8;
            CP_ASYNC16(bs + (r * B_LD + cc) * 2,
                       g_w1bf + (size_t)(k0 + r) * HH + bn + cc);
        }
        CP_COMMIT();
    };

    prefetch(0); prefetch(1); prefetch(2);

    const int NIT = DD / BK;   // 24
    for (int it = 0; it < NIT; it++) {
        CP_WAIT(2);
        __syncthreads();
        if (it + 3 < NIT) prefetch(it + 3);
        const __nv_bfloat16* st = sm + (it % STAGES) * STG_BF;
        const __nv_bfloat16* as = st;
        const __nv_bfloat16* bs = st + A_STG;
#pragma unroll
        for (int kk = 0; kk < BK; kk += 16) {
            wmma::fragment<wmma::matrix_a, 16, 16, 16, __nv_bfloat16, wmma::row_major> fa[4];
            wmma::fragment<wmma::matrix_b, 16, 16, 16, __nv_bfloat16, wmma::row_major> fb[2];
#pragma unroll
            for (int i = 0; i < 4; i++)
                wmma::load_matrix_sync(fa[i], as + (wm + i * 16) * A_LD + kk, A_LD);
#pragma unroll
            for (int j = 0; j < 2; j++)
                wmma::load_matrix_sync(fb[j], bs + kk * B_LD + wn + j * 16, B_LD);
#pragma unroll
            for (int i = 0; i < 4; i++)
#pragma unroll
                for (int j = 0; j < 2; j++)
                    wmma::mma_sync(acc[i][j], fa[i], fb[j], acc[i][j]);
        }
    }
    __syncthreads();

    // ---- Epilogue: fp32 tile in smem, bf16 h store + masked stats ----
    float* tile = (float*)sm;                 // [128][TILE_LD] = 67.6 KB
    float* cs = tile + BM * TILE_LD;
    float* cq = cs + BM;
    int*   mk = (int*)(cq + BM);

#pragma unroll
    for (int i = 0; i < 4; i++)
#pragma unroll
        for (int j = 0; j < 2; j++)
            wmma::store_matrix_sync(tile + (wm + i * 16) * TILE_LD + wn + j * 16,
                                    acc[i][j], TILE_LD, wmma::mem_row_major);
    if (t < 128) mk[t] = mask[bm + t];
    __syncthreads();

    __nv_bfloat162* H2 = (__nv_bfloat162*)g_hbf;
#pragma unroll
    for (int i = t; i < BM * 64; i += 256) {
        int r = i >> 6, c2 = (i & 63);
        float x = tile[r * TILE_LD + 2 * c2];
        float y = tile[r * TILE_LD + 2 * c2 + 1];
        H2[((size_t)(bm + r) * HH + bn) / 2 + c2] = __floats2bfloat162_rn(x, y);
    }

    int col = t & 127, half = t >> 7;
    float s = 0.f, q = 0.f;
    int rbeg = half * 64;
#pragma unroll 4
    for (int r = rbeg; r < rbeg + 64; r++) {
        if (mk[r]) {
            float v = tile[r * TILE_LD + col];
            s += v;
            q += v * v;
        }
    }
    if (half == 0) { cs[col] = s; cq[col] = q; }
    __syncthreads();
    if (half == 1) { cs[col] += s; cq[col] += q; }
    __syncthreads();
    if (t < 128) {
        atomicAdd(&g_sum[bn + t], cs[t]);
        atomicAdd(&g_sumsq[bn + t], cq[t]);
    }
}

// ---------------------------------------------------------------------------
// Pool: fused finalize + normalize + ReLU + masked sum (bf16 h read)
// ---------------------------------------------------------------------------
__global__ void k_pool(const int* __restrict__ mask, const float* __restrict__ gamma,
                       const float* __restrict__ beta) {
    int b = blockIdx.x, c = threadIdx.x, l0 = blockIdx.y * 256;
    float n = 0.f;
#pragma unroll
    for (int i = 0; i < BATCH; i++) n += g_cnt[i];
    n = fmaxf(n, 1.f);
    float mean = g_sum[c] / n;
    float var = g_sumsq[c] / n - mean * mean;
    float rs = rsqrtf(fmaxf(var, 0.f) + EPSF) * gamma[c];
    float be = beta[c];
    float s = 0.f;
    const size_t base = (size_t)(b * SEQ + l0) * HH;
    const int* mrow = mask + b * SEQ + l0;
#pragma unroll 4
    for (int l = 0; l < 256; l++) {
        if (mrow[l]) {
            float v = __bfloat162float(g_hbf[base + (size_t)l * HH + c]);
            s += fmaxf((v - mean) * rs + be, 0.f);
        }
    }
    atomicAdd(&g_pool[b * HH + c], s);
}

// ---------------------------------------------------------------------------
// GEMM2: out[b,k] = (pool[b,:]/cnt[b]) @ W2[:,k] + b2[k]
// grid (8, 32): 64 k per block, 4-way c-split, smem reduce. 256 blocks.
// ---------------------------------------------------------------------------
__global__ void __launch_bounds__(256) k_gemm2(const float* __restrict__ W2,
                                               const float* __restrict__ b2,
                                               float* __restrict__ out) {
    __shared__ float ph[HH];
    __shared__ float red[4][64];
    const int b = blockIdx.y, t = threadIdx.x;
    const int kk = t & 63, cg = t >> 6;
    const int k = blockIdx.x * 64 + kk;
    const float inv = 1.f / fmaxf(g_cnt[b], 1.f);
    for (int i = t; i < HH; i += 256) ph[i] = g_pool[b * HH + i] * inv;
    __syncthreads();
    float acc = 0.f;
    const float* w = W2 + (size_t)(cg * 128) * HH + k;
    const float* p = ph + cg * 128;
#pragma unroll 16
    for (int c = 0; c < 128; c++) acc += p[c] * w[(size_t)c * HH];
    red[cg][kk] = acc;
    __syncthreads();
    if (cg == 0)
        out[b * HH + k] = b2[k] + red[0][kk] + red[1][kk] + red[2][kk] + red[3][kk];
}

// ---------------------------------------------------------------------------
extern "C" void kernel_launch(void* const* d_in, const int* in_sizes, int n_in,
                              void* d_out, int out_size) {
    const float* hidden = (const float*)d_in[0];
    const int*   mask   = (const int*)d_in[1];
    const float* W1     = (const float*)d_in[2];
    // d_in[3] = b1: cancelled by batch-norm mean subtraction
    const float* gamma  = (const float*)d_in[4];
    const float* beta   = (const float*)d_in[5];
    const float* W2     = (const float*)d_in[6];
    const float* b2     = (const float*)d_in[7];
    float* out = (float*)d_out;

    cudaFuncSetAttribute(k_gemm1, cudaFuncAttributeMaxDynamicSharedMemorySize,
                         SMEM_BYTES);

    k_pre<<<PRE_BLOCKS, 256>>>(hidden, W1, mask);
    k_gemm1<<<dim3(HH / BN, BL / BM), 256, SMEM_BYTES>>>(mask);
    k_pool<<<dim3(BATCH, SEQ / 256), HH>>>(mask, gamma, beta);
    k_gemm2<<<dim3(8, BATCH), 256>>>(W2, b2, out);
}

// round 12
// speedup vs baseline: 3.5416x; 1.3707x over previous
#include <cuda_runtime.h>
#include <cuda_bf16.h>
#include <mma.h>
#include <cstdint>

using namespace nvcuda;

#define BATCH 32
#define SEQ   2048
#define BL    65536
#define DD    768
#define HH    512
#define EPSF  1e-5f
#define NCHUNK 8              // 2048 / 256 chunks per batch

// ---------------------------------------------------------------------------
// Static scratch
// ---------------------------------------------------------------------------
__device__ __nv_bfloat16 g_abf[(size_t)BL * DD];   // compacted bf16 hidden
__device__ __nv_bfloat16 g_w1bf[DD * HH];
__device__ __nv_bfloat16 g_hbf[(size_t)BL * HH];   // compacted activations
__device__ float g_sum[HH];
__device__ float g_sumsq[HH];
__device__ int   g_chunkcnt[BATCH * NCHUNK];
__device__ int   g_choff[BATCH * NCHUNK];          // dst offset of each chunk
__device__ int   g_cnti[BATCH];
__device__ float g_cntf[BATCH];
__device__ int   g_total_i;
__device__ int   g_ntiles_i;
__device__ float g_pool[BATCH * HH];

// ---------------------------------------------------------------------------
__device__ __forceinline__ unsigned smem_u32(const void* p) {
    return (unsigned)__cvta_generic_to_shared(p);
}
#define CP_ASYNC16(sa, ga) \
    asm volatile("cp.async.cg.shared.global [%0], [%1], 16;\n" :: "r"(sa), "l"(ga))
#define CP_COMMIT() asm volatile("cp.async.commit_group;\n" ::)
#define CP_WAIT(n)  asm volatile("cp.async.wait_group %0;\n" :: "n"(n))

// ---------------------------------------------------------------------------
// k_scan: blocks 0..31 -> per-(batch,chunk) valid counts; 32..79 -> W1 to bf16
// ---------------------------------------------------------------------------
__global__ void k_scan(const float* __restrict__ W1, const int* __restrict__ mask) {
    int blk = blockIdx.x, t = threadIdx.x;
    if (blk < BATCH) {
        __shared__ int wsum[NCHUNK][8];
        int warp = t >> 5, lane = t & 31;
#pragma unroll
        for (int ch = 0; ch < NCHUNK; ch++) {
            int m = mask[blk * SEQ + ch * 256 + t];
            unsigned bal = __ballot_sync(0xFFFFFFFFu, m);
            if (lane == 0) wsum[ch][warp] = __popc(bal);
        }
        __syncthreads();
        if (t < NCHUNK) {
            int s = 0;
#pragma unroll
            for (int w = 0; w < 8; w++) s += wsum[t][w];
            g_chunkcnt[blk * NCHUNK + t] = s;
        }
    } else {
        int b = blk - BATCH;   // 0..47
        const float4* src = (const float4*)W1;
        uint2* dst = (uint2*)g_w1bf;
#pragma unroll
        for (int j = 0; j < 8; j++) {
            int idx = b * 2048 + j * 256 + t;
            float4 v = src[idx];
            __nv_bfloat162 p0 = __floats2bfloat162_rn(v.x, v.y);
            __nv_bfloat162 p1 = __floats2bfloat162_rn(v.z, v.w);
            dst[idx] = make_uint2(*(uint32_t*)&p0, *(uint32_t*)&p1);
        }
    }
}

// ---------------------------------------------------------------------------
// k_offsets: single block. Serial prefix over 256 chunk counts; zero padding
// rows of g_abf and all accumulators.
// ---------------------------------------------------------------------------
__global__ void k_offsets() {
    __shared__ int sh_total, sh_ntiles;
    int t = threadIdx.x;
    if (t == 0) {
        int run = 0;
        for (int b = 0; b < BATCH; b++) {
            int bs = run;
            for (int ch = 0; ch < NCHUNK; ch++) {
                g_choff[b * NCHUNK + ch] = run;
                run += g_chunkcnt[b * NCHUNK + ch];
            }
            g_cnti[b] = run - bs;
            g_cntf[b] = (float)(run - bs);
        }
        g_total_i = run;
        int nt = (run + 127) >> 7;
        g_ntiles_i = nt;
        sh_total = run;
        sh_ntiles = nt;
    }
    __syncthreads();
    int total = sh_total, ntiles = sh_ntiles;
    // zero padding rows so their h==0 (harmless to stats)
    int padrows = ntiles * 128 - total;
    uint32_t* pz = (uint32_t*)(g_abf + (size_t)total * DD);
    for (int i = t; i < padrows * (DD / 2); i += 256) pz[i] = 0;
    for (int i = t; i < HH; i += 256) { g_sum[i] = 0.f; g_sumsq[i] = 0.f; }
    for (int i = t; i < BATCH * HH; i += 256) g_pool[i] = 0.f;
}

// ---------------------------------------------------------------------------
// k_compact: grid 256 = (batch,chunk). Stable local scan -> dst row; copy
// valid rows fp32 -> bf16 into compacted g_abf.
// ---------------------------------------------------------------------------
__global__ void __launch_bounds__(256) k_compact(const float* __restrict__ A,
                                                 const int* __restrict__ mask) {
    __shared__ int sc[256];
    __shared__ int sdst[256];
    const int blk = blockIdx.x, t = threadIdx.x;
    const int b = blk >> 3, ch = blk & 7;
    const int srcrow0 = b * SEQ + ch * 256;

    int m = mask[srcrow0 + t];
    sc[t] = m;
    __syncthreads();
    for (int o = 1; o < 256; o <<= 1) {
        int v = (t >= o) ? sc[t - o] : 0;
        __syncthreads();
        sc[t] += v;
        __syncthreads();
    }
    sdst[t] = m ? (g_choff[blk] + sc[t] - 1) : -1;
    __syncthreads();

    const float4* src = (const float4*)A + (size_t)srcrow0 * (DD / 4);
    uint2* dstbase = (uint2*)g_abf;
    // 256 rows x 192 float4 chunks, flat-coalesced
    for (int i = t; i < 256 * (DD / 4); i += 256) {
        int r = i / (DD / 4);
        int c = i - r * (DD / 4);
        int d = sdst[r];
        if (d >= 0) {
            float4 v = src[i];
            __nv_bfloat162 p0 = __floats2bfloat162_rn(v.x, v.y);
            __nv_bfloat162 p1 = __floats2bfloat162_rn(v.z, v.w);
            dstbase[(size_t)d * (DD / 4) + c] = make_uint2(*(uint32_t*)&p0, *(uint32_t*)&p1);
        }
    }
}

// ---------------------------------------------------------------------------
// GEMM1 on compacted rows: bf16 wmma, 4-stage cp.async, 2 CTAs/SM.
// Epilogue: bf16 h store + per-channel sum/sumsq (no mask needed).
// ---------------------------------------------------------------------------
#define BM 128
#define BN 128
#define BK 32
#define STAGES 4
#define A_LD 40
#define B_LD 136
#define A_STG (BM * A_LD)
#define B_STG (BK * B_LD)
#define STG_BF (A_STG + B_STG)
#define SMEM_BYTES (STAGES * STG_BF * 2)
#define TILE_LD 132

__global__ void __launch_bounds__(256, 2) k_gemm1() {
    if ((int)blockIdx.y >= g_ntiles_i) return;
    extern __shared__ __nv_bfloat16 sm[];

    const int bn = blockIdx.x * BN;
    const int bm = blockIdx.y * BM;
    const int t = threadIdx.x;
    const int warp = t >> 5;
    const int wm = (warp >> 2) * 64;
    const int wn = (warp & 3) * 32;

    wmma::fragment<wmma::accumulator, 16, 16, 16, float> acc[4][2];
#pragma unroll
    for (int i = 0; i < 4; i++)
#pragma unroll
        for (int j = 0; j < 2; j++) wmma::fill_fragment(acc[i][j], 0.f);

    auto prefetch = [&](int it) {
        const int k0 = it * BK;
        __nv_bfloat16* st = sm + (it % STAGES) * STG_BF;
        uint32_t as = smem_u32(st);
        uint32_t bs = smem_u32(st + A_STG);
#pragma unroll
        for (int j = 0; j < 2; j++) {
            int c = j * 256 + t;
            int r = c >> 2, cc = (c & 3) * 8;
            CP_ASYNC16(as + (r * A_LD + cc) * 2,
                       g_abf + (size_t)(bm + r) * DD + k0 + cc);
        }
#pragma unroll
        for (int j = 0; j < 2; j++) {
            int c = j * 256 + t;
            int r = c >> 4, cc = (c & 15) * 8;
            CP_ASYNC16(bs + (r * B_LD + cc) * 2,
                       g_w1bf + (size_t)(k0 + r) * HH + bn + cc);
        }
        CP_COMMIT();
    };

    prefetch(0); prefetch(1); prefetch(2);

    const int NIT = DD / BK;   // 24
    for (int it = 0; it < NIT; it++) {
        CP_WAIT(2);
        __syncthreads();
        if (it + 3 < NIT) prefetch(it + 3);
        const __nv_bfloat16* as = sm + (it % STAGES) * STG_BF;
        const __nv_bfloat16* bs = as + A_STG;
#pragma unroll
        for (int kk = 0; kk < BK; kk += 16) {
            wmma::fragment<wmma::matrix_a, 16, 16, 16, __nv_bfloat16, wmma::row_major> fa[4];
            wmma::fragment<wmma::matrix_b, 16, 16, 16, __nv_bfloat16, wmma::row_major> fb[2];
#pragma unroll
            for (int i = 0; i < 4; i++)
                wmma::load_matrix_sync(fa[i], as + (wm + i * 16) * A_LD + kk, A_LD);
#pragma unroll
            for (int j = 0; j < 2; j++)
                wmma::load_matrix_sync(fb[j], bs + kk * B_LD + wn + j * 16, B_LD);
#pragma unroll
            for (int i = 0; i < 4; i++)
#pragma unroll
                for (int j = 0; j < 2; j++)
                    wmma::mma_sync(acc[i][j], fa[i], fb[j], acc[i][j]);
        }
    }
    __syncthreads();

    // ---- Epilogue ----
    float* tile = (float*)sm;                 // [128][TILE_LD]
    float* cs = tile + BM * TILE_LD;
    float* cq = cs + BM;

#pragma unroll
    for (int i = 0; i < 4; i++)
#pragma unroll
        for (int j = 0; j < 2; j++)
            wmma::store_matrix_sync(tile + (wm + i * 16) * TILE_LD + wn + j * 16,
                                    acc[i][j], TILE_LD, wmma::mem_row_major);
    __syncthreads();

    __nv_bfloat162* H2 = (__nv_bfloat162*)g_hbf;
#pragma unroll
    for (int i = t; i < BM * 64; i += 256) {
        int r = i >> 6, c2 = (i & 63);
        float x = tile[r * TILE_LD + 2 * c2];
        float y = tile[r * TILE_LD + 2 * c2 + 1];
        H2[((size_t)(bm + r) * HH + bn) / 2 + c2] = __floats2bfloat162_rn(x, y);
    }

    // per-channel sum/sumsq over all 128 rows (padding rows are zero)
    int col = t & 127, half = t >> 7;
    float s = 0.f, q = 0.f;
    int rbeg = half * 64;
#pragma unroll 8
    for (int r = rbeg; r < rbeg + 64; r++) {
        float v = tile[r * TILE_LD + col];
        s += v;
        q += v * v;
    }
    if (half == 0) { cs[col] = s; cq[col] = q; }
    __syncthreads();
    if (half == 1) { cs[col] += s; cq[col] += q; }
    __syncthreads();
    if (t < 128) {
        atomicAdd(&g_sum[bn + t], cs[t]);
        atomicAdd(&g_sumsq[bn + t], cq[t]);
    }
}

// ---------------------------------------------------------------------------
// Pool over compacted segments: finalize + normalize + ReLU + segment sum
// ---------------------------------------------------------------------------
__global__ void k_pool(const float* __restrict__ gamma, const float* __restrict__ beta) {
    int b = blockIdx.x, ch = blockIdx.y, c = threadIdx.x;
    int cnt = g_cnti[b];
    if (ch * 256 >= cnt) return;
    int lim = min(256, cnt - ch * 256);
    int off = g_choff[b * NCHUNK];            // segment start = first chunk offset

    float n = fmaxf((float)g_total_i, 1.f);
    float mean = g_sum[c] / n;
    float var = g_sumsq[c] / n - mean * mean;
    float rs = rsqrtf(fmaxf(var, 0.f) + EPSF) * gamma[c];
    float be = beta[c];

    const __nv_bfloat16* hrow = g_hbf + (size_t)(off + ch * 256) * HH + c;
    float s = 0.f;
#pragma unroll 4
    for (int l = 0; l < lim; l++) {
        float v = __bfloat162float(hrow[(size_t)l * HH]);
        s += fmaxf((v - mean) * rs + be, 0.f);
    }
    atomicAdd(&g_pool[b * HH + c], s);
}

// ---------------------------------------------------------------------------
// GEMM2 on pooled features
// ---------------------------------------------------------------------------
__global__ void __launch_bounds__(256) k_gemm2(const float* __restrict__ W2,
                                               const float* __restrict__ b2,
                                               float* __restrict__ out) {
    __shared__ float ph[HH];
    __shared__ float red[4][64];
    const int b = blockIdx.y, t = threadIdx.x;
    const int kk = t & 63, cg = t >> 6;
    const int k = blockIdx.x * 64 + kk;
    const float inv = 1.f / fmaxf(g_cntf[b], 1.f);
    for (int i = t; i < HH; i += 256) ph[i] = g_pool[b * HH + i] * inv;
    __syncthreads();
    float acc = 0.f;
    const float* w = W2 + (size_t)(cg * 128) * HH + k;
    const float* p = ph + cg * 128;
#pragma unroll 16
    for (int c = 0; c < 128; c++) acc += p[c] * w[(size_t)c * HH];
    red[cg][kk] = acc;
    __syncthreads();
    if (cg == 0)
        out[b * HH + k] = b2[k] + red[0][kk] + red[1][kk] + red[2][kk] + red[3][kk];
}

// ---------------------------------------------------------------------------
extern "C" void kernel_launch(void* const* d_in, const int* in_sizes, int n_in,
                              void* d_out, int out_size) {
    const float* hidden = (const float*)d_in[0];
    const int*   mask   = (const int*)d_in[1];
    const float* W1     = (const float*)d_in[2];
    // d_in[3] = b1: cancelled by batch-norm mean subtraction
    const float* gamma  = (const float*)d_in[4];
    const float* beta   = (const float*)d_in[5];
    const float* W2     = (const float*)d_in[6];
    const float* b2     = (const float*)d_in[7];
    float* out = (float*)d_out;

    cudaFuncSetAttribute(k_gemm1, cudaFuncAttributeMaxDynamicSharedMemorySize,
                         SMEM_BYTES);

    k_scan<<<BATCH + 48, 256>>>(W1, mask);
    k_offsets<<<1, 256>>>();
    k_compact<<<BATCH * NCHUNK, 256>>>(hidden, mask);
    k_gemm1<<<dim3(HH / BN, BL / BM), 256, SMEM_BYTES>>>();
    k_pool<<<dim3(BATCH, NCHUNK), HH>>>(gamma, beta);
    k_gemm2<<<dim3(8, BATCH), 256>>>(W2, b2, out);
}

// round 15
// speedup vs baseline: 4.2382x; 1.1967x over previous
#include <cuda_runtime.h>
#include <cuda_bf16.h>
#include <mma.h>
#include <cstdint>

using namespace nvcuda;

#define BATCH 32
#define SEQ   2048
#define BL    65536
#define DD    768
#define HH    512
#define EPSF  1e-5f
#define NCHUNK 8              // 2048 / 256 chunks per batch

// ---------------------------------------------------------------------------
// Static scratch
// ---------------------------------------------------------------------------
__device__ __nv_bfloat16 g_abf[(size_t)BL * DD];   // compacted bf16 hidden
__device__ __nv_bfloat16 g_w1bf[DD * HH];
__device__ __nv_bfloat16 g_hbf[(size_t)BL * HH];   // compacted activations
__device__ float g_sum[HH];
__device__ float g_sumsq[HH];
__device__ int   g_chunkcnt[BATCH * NCHUNK];
__device__ int   g_choff[BATCH * NCHUNK];
__device__ int   g_cnti[BATCH];
__device__ float g_cntf[BATCH];
__device__ int   g_total_i;
__device__ int   g_ntiles_i;
__device__ float g_pool[BATCH * HH];

// ---------------------------------------------------------------------------
__device__ __forceinline__ unsigned smem_u32(const void* p) {
    return (unsigned)__cvta_generic_to_shared(p);
}
#define CP_ASYNC16(sa, ga) \
    asm volatile("cp.async.cg.shared.global [%0], [%1], 16;\n" :: "r"(sa), "l"(ga))
#define CP_COMMIT() asm volatile("cp.async.commit_group;\n" ::)
#define CP_WAIT(n)  asm volatile("cp.async.wait_group %0;\n" :: "n"(n))

// ---------------------------------------------------------------------------
// k_scan: blocks 0..31 -> per-(batch,chunk) counts; 32..79 -> W1 to bf16
// ---------------------------------------------------------------------------
__global__ void k_scan(const float* __restrict__ W1, const int* __restrict__ mask) {
    int blk = blockIdx.x, t = threadIdx.x;
    if (blk < BATCH) {
        __shared__ int wsum[NCHUNK][8];
        int warp = t >> 5, lane = t & 31;
#pragma unroll
        for (int ch = 0; ch < NCHUNK; ch++) {
            int m = mask[blk * SEQ + ch * 256 + t];
            unsigned bal = __ballot_sync(0xFFFFFFFFu, m);
            if (lane == 0) wsum[ch][warp] = __popc(bal);
        }
        __syncthreads();
        if (t < NCHUNK) {
            int s = 0;
#pragma unroll
            for (int w = 0; w < 8; w++) s += wsum[t][w];
            g_chunkcnt[blk * NCHUNK + t] = s;
        }
    } else {
        int b = blk - BATCH;   // 0..47
        const float4* src = (const float4*)W1;
        uint2* dst = (uint2*)g_w1bf;
#pragma unroll
        for (int j = 0; j < 8; j++) {
            int idx = b * 2048 + j * 256 + t;
            float4 v = src[idx];
            __nv_bfloat162 p0 = __floats2bfloat162_rn(v.x, v.y);
            __nv_bfloat162 p1 = __floats2bfloat162_rn(v.z, v.w);
            dst[idx] = make_uint2(*(uint32_t*)&p0, *(uint32_t*)&p1);
        }
    }
}

// ---------------------------------------------------------------------------
// k_offsets: single block. Serial prefix; zero padding rows + accumulators.
// ---------------------------------------------------------------------------
__global__ void k_offsets() {
    __shared__ int sh_total, sh_ntiles;
    int t = threadIdx.x;
    if (t == 0) {
        int run = 0;
        for (int b = 0; b < BATCH; b++) {
            int bs = run;
            for (int ch = 0; ch < NCHUNK; ch++) {
                g_choff[b * NCHUNK + ch] = run;
                run += g_chunkcnt[b * NCHUNK + ch];
            }
            g_cnti[b] = run - bs;
            g_cntf[b] = (float)(run - bs);
        }
        g_total_i = run;
        int nt = (run + 127) >> 7;
        g_ntiles_i = nt;
        sh_total = run;
        sh_ntiles = nt;
    }
    __syncthreads();
    int total = sh_total, ntiles = sh_ntiles;
    int padrows = ntiles * 128 - total;
    uint32_t* pz = (uint32_t*)(g_abf + (size_t)total * DD);
    for (int i = t; i < padrows * (DD / 2); i += 256) pz[i] = 0;
    for (int i = t; i < HH; i += 256) { g_sum[i] = 0.f; g_sumsq[i] = 0.f; }
    for (int i = t; i < BATCH * HH; i += 256) g_pool[i] = 0.f;
}

// ---------------------------------------------------------------------------
// k_compact: stable local scan -> dst row; fp32 -> bf16 row copy
// ---------------------------------------------------------------------------
__global__ void __launch_bounds__(256) k_compact(const float* __restrict__ A,
                                                 const int* __restrict__ mask) {
    __shared__ int sc[256];
    __shared__ int sdst[256];
    const int blk = blockIdx.x, t = threadIdx.x;
    const int b = blk >> 3, ch = blk & 7;
    const int srcrow0 = b * SEQ + ch * 256;

    int m = mask[srcrow0 + t];
    sc[t] = m;
    __syncthreads();
    for (int o = 1; o < 256; o <<= 1) {
        int v = (t >= o) ? sc[t - o] : 0;
        __syncthreads();
        sc[t] += v;
        __syncthreads();
    }
    sdst[t] = m ? (g_choff[blk] + sc[t] - 1) : -1;
    __syncthreads();

    const float4* src = (const float4*)A + (size_t)srcrow0 * (DD / 4);
    uint2* dstbase = (uint2*)g_abf;
#pragma unroll 4
    for (int i = t; i < 256 * (DD / 4); i += 256) {
        int r = i / (DD / 4);
        int c = i - r * (DD / 4);
        int d = sdst[r];
        if (d >= 0) {
            float4 v = src[i];
            __nv_bfloat162 p0 = __floats2bfloat162_rn(v.x, v.y);
            __nv_bfloat162 p1 = __floats2bfloat162_rn(v.z, v.w);
            dstbase[(size_t)d * (DD / 4) + c] = make_uint2(*(uint32_t*)&p0, *(uint32_t*)&p1);
        }
    }
}

// ---------------------------------------------------------------------------
// GEMM1 on compacted rows: bf16 wmma, BK=64, 3-stage cp.async, 2 CTAs/SM.
// ---------------------------------------------------------------------------
#define BM 128
#define BN 128
#define BK 64
#define STAGES 3
#define A_LD 72     // 64 + 8 pad
#define B_LD 136    // 128 + 8 pad
#define A_STG (BM * A_LD)          // 9216 bf16 (18432 B)
#define B_STG (BK * B_LD)          // 8704 bf16 (17408 B)
#define STG_BF (A_STG + B_STG)     // 17920 bf16 (35840 B)
#define SMEM_BYTES (STAGES * STG_BF * 2)   // 107520 B (x2 CTAs = 215 KB)
#define TILE_LD 132

__global__ void __launch_bounds__(256, 2) k_gemm1() {
    if ((int)blockIdx.y >= g_ntiles_i) return;
    extern __shared__ __nv_bfloat16 sm[];

    const int bn = blockIdx.x * BN;
    const int bm = blockIdx.y * BM;
    const int t = threadIdx.x;
    const int warp = t >> 5;
    const int wm = (warp >> 2) * 64;
    const int wn = (warp & 3) * 32;

    wmma::fragment<wmma::accumulator, 16, 16, 16, float> acc[4][2];
#pragma unroll
    for (int i = 0; i < 4; i++)
#pragma unroll
        for (int j = 0; j < 2; j++) wmma::fill_fragment(acc[i][j], 0.f);

    auto prefetch = [&](int it) {
        const int k0 = it * BK;
        __nv_bfloat16* st = sm + (it % STAGES) * STG_BF;
        uint32_t as = smem_u32(st);
        uint32_t bs = smem_u32(st + A_STG);
        // A tile: 128 rows x 64 bf16 = 1024 16B-chunks
#pragma unroll
        for (int j = 0; j < 4; j++) {
            int c = j * 256 + t;
            int r = c >> 3, cc = (c & 7) * 8;
            CP_ASYNC16(as + (r * A_LD + cc) * 2,
                       g_abf + (size_t)(bm + r) * DD + k0 + cc);
        }
        // B tile: 64 rows x 128 bf16 = 1024 chunks
#pragma unroll
        for (int j = 0; j < 4; j++) {
            int c = j * 256 + t;
            int r = c >> 4, cc = (c & 15) * 8;
            CP_ASYNC16(bs + (r * B_LD + cc) * 2,
                       g_w1bf + (size_t)(k0 + r) * HH + bn + cc);
        }
        CP_COMMIT();
    };

    prefetch(0); prefetch(1);

    const int NIT = DD / BK;   // 12
    for (int it = 0; it < NIT; it++) {
        CP_WAIT(1);
        __syncthreads();
        if (it + 2 < NIT) prefetch(it + 2);
        const __nv_bfloat16* as = sm + (it % STAGES) * STG_BF;
        const __nv_bfloat16* bs = as + A_STG;
#pragma unroll
        for (int kk = 0; kk < BK; kk += 16) {
            wmma::fragment<wmma::matrix_a, 16, 16, 16, __nv_bfloat16, wmma::row_major> fa[4];
            wmma::fragment<wmma::matrix_b, 16, 16, 16, __nv_bfloat16, wmma::row_major> fb[2];
#pragma unroll
            for (int i = 0; i < 4; i++)
                wmma::load_matrix_sync(fa[i], as + (wm + i * 16) * A_LD + kk, A_LD);
#pragma unroll
            for (int j = 0; j < 2; j++)
                wmma::load_matrix_sync(fb[j], bs + kk * B_LD + wn + j * 16, B_LD);
#pragma unroll
            for (int i = 0; i < 4; i++)
#pragma unroll
                for (int j = 0; j < 2; j++)
                    wmma::mma_sync(acc[i][j], fa[i], fb[j], acc[i][j]);
        }
    }
    __syncthreads();

    // ---- Epilogue: fp32 tile (aliases pipe smem), bf16 h store + stats ----
    float* tile = (float*)sm;                 // [128][TILE_LD] = 67584 B
    float* cs = tile + BM * TILE_LD;
    float* cq = cs + BM;

#pragma unroll
    for (int i = 0; i < 4; i++)
#pragma unroll
        for (int j = 0; j < 2; j++)
            wmma::store_matrix_sync(tile + (wm + i * 16) * TILE_LD + wn + j * 16,
                                    acc[i][j], TILE_LD, wmma::mem_row_major);
    __syncthreads();

    __nv_bfloat162* H2 = (__nv_bfloat162*)g_hbf;
#pragma unroll
    for (int i = t; i < BM * 64; i += 256) {
        int r = i >> 6, c2 = (i & 63);
        float x = tile[r * TILE_LD + 2 * c2];
        float y = tile[r * TILE_LD + 2 * c2 + 1];
        H2[((size_t)(bm + r) * HH + bn) / 2 + c2] = __floats2bfloat162_rn(x, y);
    }

    int col = t & 127, half = t >> 7;
    float s = 0.f, q = 0.f;
    int rbeg = half * 64;
#pragma unroll 8
    for (int r = rbeg; r < rbeg + 64; r++) {
        float v = tile[r * TILE_LD + col];
        s += v;
        q += v * v;
    }
    if (half == 0) { cs[col] = s; cq[col] = q; }
    __syncthreads();
    if (half == 1) { cs[col] += s; cq[col] += q; }
    __syncthreads();
    if (t < 128) {
        atomicAdd(&g_sum[bn + t], cs[t]);
        atomicAdd(&g_sumsq[bn + t], cq[t]);
    }
}

// ---------------------------------------------------------------------------
// Pool: 128-row chunks, 8-way MLP. finalize + normalize + ReLU + segment sum
// ---------------------------------------------------------------------------
#define PCH 16   // 2048/128 chunks per batch
__global__ void __launch_bounds__(512) k_pool(const float* __restrict__ gamma,
                                              const float* __restrict__ beta) {
    int b = blockIdx.x, ch = blockIdx.y, c = threadIdx.x;
    int cnt = g_cnti[b];
    int r0 = ch * 128;
    if (r0 >= cnt) return;
    int lim = min(128, cnt - r0);
    int off = g_choff[b * NCHUNK];

    float n = fmaxf((float)g_total_i, 1.f);
    float mean = g_sum[c] / n;
    float var = g_sumsq[c] / n - mean * mean;
    float rs = rsqrtf(fmaxf(var, 0.f) + EPSF) * gamma[c];
    float be = beta[c];

    const __nv_bfloat16* hrow = g_hbf + (size_t)(off + r0) * HH + c;
    float s = 0.f;
    int l = 0;
    for (; l + 8 <= lim; l += 8) {
        float v0 = __bfloat162float(hrow[(size_t)(l + 0) * HH]);
        float v1 = __bfloat162float(hrow[(size_t)(l + 1) * HH]);
        float v2 = __bfloat162float(hrow[(size_t)(l + 2) * HH]);
        float v3 = __bfloat162float(hrow[(size_t)(l + 3) * HH]);
        float v4 = __bfloat162float(hrow[(size_t)(l + 4) * HH]);
        float v5 = __bfloat162float(hrow[(size_t)(l + 5) * HH]);
        float v6 = __bfloat162float(hrow[(size_t)(l + 6) * HH]);
        float v7 = __bfloat162float(hrow[(size_t)(l + 7) * HH]);
        s += fmaxf((v0 - mean) * rs + be, 0.f);
        s += fmaxf((v1 - mean) * rs + be, 0.f);
        s += fmaxf((v2 - mean) * rs + be, 0.f);
        s += fmaxf((v3 - mean) * rs + be, 0.f);
        s += fmaxf((v4 - mean) * rs + be, 0.f);
        s += fmaxf((v5 - mean) * rs + be, 0.f);
        s += fmaxf((v6 - mean) * rs + be, 0.f);
        s += fmaxf((v7 - mean) * rs + be, 0.f);
    }
    for (; l < lim; l++) {
        float v = __bfloat162float(hrow[(size_t)l * HH]);
        s += fmaxf((v - mean) * rs + be, 0.f);
    }
    atomicAdd(&g_pool[b * HH + c], s);
}

// ---------------------------------------------------------------------------
// GEMM2: grid (16, 32), 32 k per block, 8-way c-split
// ---------------------------------------------------------------------------
__global__ void __launch_bounds__(256) k_gemm2(const float* __restrict__ W2,
                                               const float* __restrict__ b2,
                                               float* __restrict__ out) {
    __shared__ float ph[HH];
    __shared__ float red[8][32];
    const int b = blockIdx.y, t = threadIdx.x;
    const int kk = t & 31, cg = t >> 5;
    const int k = blockIdx.x * 32 + kk;
    const float inv = 1.f / fmaxf(g_cntf[b], 1.f);
    for (int i = t; i < HH; i += 256) ph[i] = g_pool[b * HH + i] * inv;
    __syncthreads();
    float acc = 0.f;
    const float* w = W2 + (size_t)(cg * 64) * HH + k;
    const float* p = ph + cg * 64;
#pragma unroll 16
    for (int c = 0; c < 64; c++) acc += p[c] * w[(size_t)c * HH];
    red[cg][kk] = acc;
    __syncthreads();
    if (cg == 0) {
        float r = b2[k];
#pragma unroll
        for (int j = 0; j < 8; j++) r += red[j][kk];
        out[b * HH + k] = r;
    }
}

// ---------------------------------------------------------------------------
extern "C" void kernel_launch(void* const* d_in, const int* in_sizes, int n_in,
                              void* d_out, int out_size) {
    const float* hidden = (const float*)d_in[0];
    const int*   mask   = (const int*)d_in[1];
    const float* W1     = (const float*)d_in[2];
    // d_in[3] = b1: cancelled by batch-norm mean subtraction
    const float* gamma  = (const float*)d_in[4];
    const float* beta   = (const float*)d_in[5];
    const float* W2     = (const float*)d_in[6];
    const float* b2     = (const float*)d_in[7];
    float* out = (float*)d_out;

    cudaFuncSetAttribute(k_gemm1, cudaFuncAttributeMaxDynamicSharedMemorySize,
                         SMEM_BYTES);

    k_scan<<<BATCH + 48, 256>>>(W1, mask);
    k_offsets<<<1, 256>>>();
    k_compact<<<BATCH * NCHUNK, 256>>>(hidden, mask);
    k_gemm1<<<dim3(HH / BN, BL / BM), 256, SMEM_BYTES>>>();
    k_pool<<<dim3(BATCH, PCH), 512>>>(gamma, beta);
    k_gemm2<<<dim3(16, BATCH), 256>>>(W2, b2, out);
}

// round 16
// speedup vs baseline: 4.7284x; 1.1157x over previous
#include <cuda_runtime.h>
#include <cuda_bf16.h>
#include <mma.h>
#include <cstdint>

using namespace nvcuda;

#define BATCH 32
#define SEQ   2048
#define BL    65536
#define DD    768
#define HH    512
#define EPSF  1e-5f
#define NCHUNK 8              // 2048 / 256 chunks per batch

// ---------------------------------------------------------------------------
// Static scratch
// ---------------------------------------------------------------------------
__device__ __nv_bfloat16 g_abf[(size_t)BL * DD];   // compacted bf16 hidden
__device__ __nv_bfloat16 g_w1bf[DD * HH];
__device__ __nv_bfloat16 g_hbf[(size_t)BL * HH];   // compacted activations
__device__ float g_sum[HH];
__device__ float g_sumsq[HH];
__device__ int   g_chunkcnt[BATCH * NCHUNK];       // 256 per-(batch,chunk) counts
__device__ int   g_boff[BATCH];                    // batch start offset (compacted)
__device__ int   g_cnti[BATCH];
__device__ float g_cntf[BATCH];
__device__ int   g_total_i;
__device__ int   g_ntiles_i;
__device__ float g_pool[BATCH * HH];

// ---------------------------------------------------------------------------
__device__ __forceinline__ unsigned smem_u32(const void* p) {
    return (unsigned)__cvta_generic_to_shared(p);
}
#define CP_ASYNC16(sa, ga) \
    asm volatile("cp.async.cg.shared.global [%0], [%1], 16;\n" :: "r"(sa), "l"(ga))
#define CP_COMMIT() asm volatile("cp.async.commit_group;\n" ::)
#define CP_WAIT(n)  asm volatile("cp.async.wait_group %0;\n" :: "n"(n))

// ---------------------------------------------------------------------------
// k_scan: blocks 0..31 counts; 32..79 W1->bf16; 80..143 zero g_pool;
// 144 zeroes g_sum/g_sumsq.
// ---------------------------------------------------------------------------
__global__ void k_scan(const float* __restrict__ W1, const int* __restrict__ mask) {
    int blk = blockIdx.x, t = threadIdx.x;
    if (blk < BATCH) {
        __shared__ int wsum[NCHUNK][8];
        int warp = t >> 5, lane = t & 31;
#pragma unroll
        for (int ch = 0; ch < NCHUNK; ch++) {
            int m = mask[blk * SEQ + ch * 256 + t];
            unsigned bal = __ballot_sync(0xFFFFFFFFu, m);
            if (lane == 0) wsum[ch][warp] = __popc(bal);
        }
        __syncthreads();
        if (t < NCHUNK) {
            int s = 0;
#pragma unroll
            for (int w = 0; w < 8; w++) s += wsum[t][w];
            g_chunkcnt[blk * NCHUNK + t] = s;
        }
    } else if (blk < BATCH + 48) {
        int b = blk - BATCH;   // 0..47
        const float4* src = (const float4*)W1;
        uint2* dst = (uint2*)g_w1bf;
#pragma unroll
        for (int j = 0; j < 8; j++) {
            int idx = b * 2048 + j * 256 + t;
            float4 v = src[idx];
            __nv_bfloat162 p0 = __floats2bfloat162_rn(v.x, v.y);
            __nv_bfloat162 p1 = __floats2bfloat162_rn(v.z, v.w);
            dst[idx] = make_uint2(*(uint32_t*)&p0, *(uint32_t*)&p1);
        }
    } else if (blk < BATCH + 48 + 64) {
        g_pool[(blk - BATCH - 48) * 256 + t] = 0.f;
    } else {
        g_sum[t] = 0.f; g_sum[t + 256] = 0.f;
        g_sumsq[t] = 0.f; g_sumsq[t + 256] = 0.f;
    }
}
#define SCAN_BLOCKS (BATCH + 48 + 64 + 1)

// ---------------------------------------------------------------------------
// k_compact: self-computed offsets (reduce over g_chunkcnt), valid-row-only
// fp32 -> bf16 copy. Block 0 publishes total/ntiles; ch==0 blocks publish
// per-batch offset/count.
// ---------------------------------------------------------------------------
__global__ void __launch_bounds__(256) k_compact(const float* __restrict__ A,
                                                 const int* __restrict__ mask) {
    __shared__ int red[256];
    __shared__ int sc[256];
    __shared__ short vr[256];
    __shared__ int sh_off, sh_nv;
    const int blk = blockIdx.x, t = threadIdx.x;
    const int srcrow0 = blk * 256;          // == b*SEQ + ch*256 (SEQ = 8*256)

    int cc = g_chunkcnt[t];
    // total across all chunks (block 0 publishes)
    red[t] = cc;
    __syncthreads();
    for (int o = 128; o > 0; o >>= 1) {
        if (t < o) red[t] += red[t + o];
        __syncthreads();
    }
    int total = red[0];
    __syncthreads();
    // this block's destination offset = sum of chunkcnt[0..blk-1]
    red[t] = (t < blk) ? cc : 0;
    __syncthreads();
    for (int o = 128; o > 0; o >>= 1) {
        if (t < o) red[t] += red[t + o];
        __syncthreads();
    }
    if (t == 0) sh_off = red[0];
    __syncthreads();
    const int offset = sh_off;

    if (blk == 0 && t == 0) {
        g_total_i = total;
        g_ntiles_i = (total + 127) >> 7;
    }
    if ((blk & 7) == 0 && t == 0) {
        int b = blk >> 3;
        g_boff[b] = offset;
        int s = 0;
#pragma unroll
        for (int ch = 0; ch < NCHUNK; ch++) s += g_chunkcnt[blk + ch];
        g_cnti[b] = s;
        g_cntf[b] = (float)s;
    }

    // stable local scan of mask -> valid-row list
    int m = mask[srcrow0 + t];
    sc[t] = m;
    __syncthreads();
    for (int o = 1; o < 256; o <<= 1) {
        int v = (t >= o) ? sc[t - o] : 0;
        __syncthreads();
        sc[t] += v;
        __syncthreads();
    }
    if (m) vr[sc[t] - 1] = (short)t;
    if (t == 255) sh_nv = sc[255];
    __syncthreads();
    const int nv = sh_nv;

    // copy only valid rows (reads 50% of A instead of 100%)
    const float4* src = (const float4*)A;
    uint2* dst = (uint2*)g_abf;
    const int NC = DD / 4;   // 192 float4 per row
    for (int i = t; i < nv * NC; i += 256) {
        int vi = i / NC, c = i - vi * NC;
        int sr = srcrow0 + vr[vi];
        float4 v = src[(size_t)sr * NC + c];
        __nv_bfloat162 p0 = __floats2bfloat162_rn(v.x, v.y);
        __nv_bfloat162 p1 = __floats2bfloat162_rn(v.z, v.w);
        dst[(size_t)(offset + vi) * NC + c] = make_uint2(*(uint32_t*)&p0, *(uint32_t*)&p1);
    }
}

// ---------------------------------------------------------------------------
// GEMM1 on compacted rows: bf16 wmma, BK=64, 3-stage cp.async, 2 CTAs/SM.
// Stats epilogue clamps to rows_valid (no padding-row zeroing needed).
// ---------------------------------------------------------------------------
#define BM 128
#define BN 128
#define BK 64
#define STAGES 3
#define A_LD 72
#define B_LD 136
#define A_STG (BM * A_LD)
#define B_STG (BK * B_LD)
#define STG_BF (A_STG + B_STG)
#define SMEM_BYTES (STAGES * STG_BF * 2)   // 107520 B
#define TILE_LD 132

__global__ void __launch_bounds__(256, 2) k_gemm1() {
    if ((int)blockIdx.y >= g_ntiles_i) return;
    extern __shared__ __nv_bfloat16 sm[];

    const int bn = blockIdx.x * BN;
    const int bm = blockIdx.y * BM;
    const int t = threadIdx.x;
    const int warp = t >> 5;
    const int wm = (warp >> 2) * 64;
    const int wn = (warp & 3) * 32;
    const int rows_valid = min(BM, g_total_i - bm);

    wmma::fragment<wmma::accumulator, 16, 16, 16, float> acc[4][2];
#pragma unroll
    for (int i = 0; i < 4; i++)
#pragma unroll
        for (int j = 0; j < 2; j++) wmma::fill_fragment(acc[i][j], 0.f);

    auto prefetch = [&](int it) {
        const int k0 = it * BK;
        __nv_bfloat16* st = sm + (it % STAGES) * STG_BF;
        uint32_t as = smem_u32(st);
        uint32_t bs = smem_u32(st + A_STG);
#pragma unroll
        for (int j = 0; j < 4; j++) {
            int c = j * 256 + t;
            int r = c >> 3, cc = (c & 7) * 8;
            CP_ASYNC16(as + (r * A_LD + cc) * 2,
                       g_abf + (size_t)(bm + r) * DD + k0 + cc);
        }
#pragma unroll
        for (int j = 0; j < 4; j++) {
            int c = j * 256 + t;
            int r = c >> 4, cc = (c & 15) * 8;
            CP_ASYNC16(bs + (r * B_LD + cc) * 2,
                       g_w1bf + (size_t)(k0 + r) * HH + bn + cc);
        }
        CP_COMMIT();
    };

    prefetch(0); prefetch(1);

    const int NIT = DD / BK;   // 12
    for (int it = 0; it < NIT; it++) {
        CP_WAIT(1);
        __syncthreads();
        if (it + 2 < NIT) prefetch(it + 2);
        const __nv_bfloat16* as = sm + (it % STAGES) * STG_BF;
        const __nv_bfloat16* bs = as + A_STG;
#pragma unroll
        for (int kk = 0; kk < BK; kk += 16) {
            wmma::fragment<wmma::matrix_a, 16, 16, 16, __nv_bfloat16, wmma::row_major> fa[4];
            wmma::fragment<wmma::matrix_b, 16, 16, 16, __nv_bfloat16, wmma::row_major> fb[2];
#pragma unroll
            for (int i = 0; i < 4; i++)
                wmma::load_matrix_sync(fa[i], as + (wm + i * 16) * A_LD + kk, A_LD);
#pragma unroll
            for (int j = 0; j < 2; j++)
                wmma::load_matrix_sync(fb[j], bs + kk * B_LD + wn + j * 16, B_LD);
#pragma unroll
            for (int i = 0; i < 4; i++)
#pragma unroll
                for (int j = 0; j < 2; j++)
                    wmma::mma_sync(acc[i][j], fa[i], fb[j], acc[i][j]);
        }
    }
    __syncthreads();

    // ---- Epilogue: fp32 tile (aliases pipe smem), bf16 h store + stats ----
    float* tile = (float*)sm;                 // [128][TILE_LD]
    float* cs = tile + BM * TILE_LD;
    float* cq = cs + BM;

#pragma unroll
    for (int i = 0; i < 4; i++)
#pragma unroll
        for (int j = 0; j < 2; j++)
            wmma::store_matrix_sync(tile + (wm + i * 16) * TILE_LD + wn + j * 16,
                                    acc[i][j], TILE_LD, wmma::mem_row_major);
    __syncthreads();

    __nv_bfloat162* H2 = (__nv_bfloat162*)g_hbf;
#pragma unroll
    for (int i = t; i < BM * 64; i += 256) {
        int r = i >> 6, c2 = (i & 63);
        float x = tile[r * TILE_LD + 2 * c2];
        float y = tile[r * TILE_LD + 2 * c2 + 1];
        H2[((size_t)(bm + r) * HH + bn) / 2 + c2] = __floats2bfloat162_rn(x, y);
    }

    // per-channel sum/sumsq over valid rows only
    int col = t & 127, half = t >> 7;
    float s = 0.f, q = 0.f;
    int rbeg = half * 64;
    int rend = min(rbeg + 64, rows_valid);
    for (int r = rbeg; r < rend; r++) {
        float v = tile[r * TILE_LD + col];
        s += v;
        q += v * v;
    }
    if (half == 0) { cs[col] = s; cq[col] = q; }
    __syncthreads();
    if (half == 1) { cs[col] += s; cq[col] += q; }
    __syncthreads();
    if (t < 128) {
        atomicAdd(&g_sum[bn + t], cs[t]);
        atomicAdd(&g_sumsq[bn + t], cq[t]);
    }
}

// ---------------------------------------------------------------------------
// Pool: 128-row chunks, 8-way MLP. finalize + normalize + ReLU + segment sum
// ---------------------------------------------------------------------------
#define PCH 16   // 2048/128 chunks per batch
__global__ void __launch_bounds__(512) k_pool(const float* __restrict__ gamma,
                                              const float* __restrict__ beta) {
    int b = blockIdx.x, ch = blockIdx.y, c = threadIdx.x;
    int cnt = g_cnti[b];
    int r0 = ch * 128;
    if (r0 >= cnt) return;
    int lim = min(128, cnt - r0);
    int off = g_boff[b];

    float n = fmaxf((float)g_total_i, 1.f);
    float mean = g_sum[c] / n;
    float var = g_sumsq[c] / n - mean * mean;
    float rs = rsqrtf(fmaxf(var, 0.f) + EPSF) * gamma[c];
    float be = beta[c];

    const __nv_bfloat16* hrow = g_hbf + (size_t)(off + r0) * HH + c;
    float s = 0.f;
    int l = 0;
    for (; l + 8 <= lim; l += 8) {
        float v0 = __bfloat162float(hrow[(size_t)(l + 0) * HH]);
        float v1 = __bfloat162float(hrow[(size_t)(l + 1) * HH]);
        float v2 = __bfloat162float(hrow[(size_t)(l + 2) * HH]);
        float v3 = __bfloat162float(hrow[(size_t)(l + 3) * HH]);
        float v4 = __bfloat162float(hrow[(size_t)(l + 4) * HH]);
        float v5 = __bfloat162float(hrow[(size_t)(l + 5) * HH]);
        float v6 = __bfloat162float(hrow[(size_t)(l + 6) * HH]);
        float v7 = __bfloat162float(hrow[(size_t)(l + 7) * HH]);
        s += fmaxf((v0 - mean) * rs + be, 0.f);
        s += fmaxf((v1 - mean) * rs + be, 0.f);
        s += fmaxf((v2 - mean) * rs + be, 0.f);
        s += fmaxf((v3 - mean) * rs + be, 0.f);
        s += fmaxf((v4 - mean) * rs + be, 0.f);
        s += fmaxf((v5 - mean) * rs + be, 0.f);
        s += fmaxf((v6 - mean) * rs + be, 0.f);
        s += fmaxf((v7 - mean) * rs + be, 0.f);
    }
    for (; l < lim; l++) {
        float v = __bfloat162float(hrow[(size_t)l * HH]);
        s += fmaxf((v - mean) * rs + be, 0.f);
    }
    atomicAdd(&g_pool[b * HH + c], s);
}

// ---------------------------------------------------------------------------
// GEMM2: grid (16, 32), 32 k per block, 8-way c-split
// ---------------------------------------------------------------------------
__global__ void __launch_bounds__(256) k_gemm2(const float* __restrict__ W2,
                                               const float* __restrict__ b2,
                                               float* __restrict__ out) {
    __shared__ float ph[HH];
    __shared__ float red[8][32];
    const int b = blockIdx.y, t = threadIdx.x;
    const int kk = t & 31, cg = t >> 5;
    const int k = blockIdx.x * 32 + kk;
    const float inv = 1.f / fmaxf(g_cntf[b], 1.f);
    for (int i = t; i < HH; i += 256) ph[i] = g_pool[b * HH + i] * inv;
    __syncthreads();
    float acc = 0.f;
    const float* w = W2 + (size_t)(cg * 64) * HH + k;
    const float* p = ph + cg * 64;
#pragma unroll 16
    for (int c = 0; c < 64; c++) acc += p[c] * w[(size_t)c * HH];
    red[cg][kk] = acc;
    __syncthreads();
    if (cg == 0) {
        float r = b2[k];
#pragma unroll
        for (int j = 0; j < 8; j++) r += red[j][kk];
        out[b * HH + k] = r;
    }
}

// ---------------------------------------------------------------------------
extern "C" void kernel_launch(void* const* d_in, const int* in_sizes, int n_in,
                              void* d_out, int out_size) {
    const float* hidden = (const float*)d_in[0];
    const int*   mask   = (const int*)d_in[1];
    const float* W1     = (const float*)d_in[2];
    // d_in[3] = b1: cancelled by batch-norm mean subtraction
    const float* gamma  = (const float*)d_in[4];
    const float* beta   = (const float*)d_in[5];
    const float* W2     = (const float*)d_in[6];
    const float* b2     = (const float*)d_in[7];
    float* out = (float*)d_out;

    cudaFuncSetAttribute(k_gemm1, cudaFuncAttributeMaxDynamicSharedMemorySize,
                         SMEM_BYTES);

    k_scan<<<SCAN_BLOCKS, 256>>>(W1, mask);
    k_compact<<<BATCH * NCHUNK, 256>>>(hidden, mask);
    k_gemm1<<<dim3(HH / BN, BL / BM), 256, SMEM_BYTES>>>();
    k_pool<<<dim3(BATCH, PCH), 512>>>(gamma, beta);
    k_gemm2<<<dim3(16, BATCH), 256>>>(W2, b2, out);
}

// round 17
// speedup vs baseline: 4.8397x; 1.0235x over previous
#include <cuda_runtime.h>
#include <cuda_bf16.h>
#include <mma.h>
#include <cstdint>

using namespace nvcuda;

#define BATCH 32
#define SEQ   2048
#define BL    65536
#define DD    768
#define HH    512
#define EPSF  1e-5f
#define NCHUNK 8              // 2048 / 256 chunks per batch

// ---------------------------------------------------------------------------
// Static scratch
// ---------------------------------------------------------------------------
__device__ __nv_bfloat16 g_abf[(size_t)BL * DD];   // compacted bf16 hidden
__device__ __nv_bfloat16 g_w1bf[DD * HH];
__device__ __nv_bfloat16 g_hbf[(size_t)BL * HH];   // compacted activations
__device__ float g_sum[HH];
__device__ float g_sumsq[HH];
__device__ int   g_chunkcnt[BATCH * NCHUNK];       // 256 per-(batch,chunk) counts
__device__ int   g_boff[BATCH];                    // batch start offset (compacted)
__device__ int   g_cnti[BATCH];
__device__ float g_cntf[BATCH];
__device__ int   g_total_i;
__device__ int   g_ntiles_i;
__device__ float g_pool[BATCH * HH];

// ---------------------------------------------------------------------------
__device__ __forceinline__ unsigned smem_u32(const void* p) {
    return (unsigned)__cvta_generic_to_shared(p);
}
#define CP_ASYNC16(sa, ga) \
    asm volatile("cp.async.cg.shared.global [%0], [%1], 16;\n" :: "r"(sa), "l"(ga))
#define CP_COMMIT() asm volatile("cp.async.commit_group;\n" ::)
#define CP_WAIT(n)  asm volatile("cp.async.wait_group %0;\n" :: "n"(n))

// ---------------------------------------------------------------------------
// k_scan: blocks 0..31 counts; 32..79 W1->bf16; 80..143 zero g_pool;
// 144 zeroes g_sum/g_sumsq.
// ---------------------------------------------------------------------------
__global__ void k_scan(const float* __restrict__ W1, const int* __restrict__ mask) {
    int blk = blockIdx.x, t = threadIdx.x;
    if (blk < BATCH) {
        __shared__ int wsum[NCHUNK][8];
        int warp = t >> 5, lane = t & 31;
#pragma unroll
        for (int ch = 0; ch < NCHUNK; ch++) {
            int m = mask[blk * SEQ + ch * 256 + t];
            unsigned bal = __ballot_sync(0xFFFFFFFFu, m);
            if (lane == 0) wsum[ch][warp] = __popc(bal);
        }
        __syncthreads();
        if (t < NCHUNK) {
            int s = 0;
#pragma unroll
            for (int w = 0; w < 8; w++) s += wsum[t][w];
            g_chunkcnt[blk * NCHUNK + t] = s;
        }
    } else if (blk < BATCH + 48) {
        int b = blk - BATCH;   // 0..47
        const float4* src = (const float4*)W1;
        uint2* dst = (uint2*)g_w1bf;
#pragma unroll
        for (int j = 0; j < 8; j++) {
            int idx = b * 2048 + j * 256 + t;
            float4 v = src[idx];
            __nv_bfloat162 p0 = __floats2bfloat162_rn(v.x, v.y);
            __nv_bfloat162 p1 = __floats2bfloat162_rn(v.z, v.w);
            dst[idx] = make_uint2(*(uint32_t*)&p0, *(uint32_t*)&p1);
        }
    } else if (blk < BATCH + 48 + 64) {
        g_pool[(blk - BATCH - 48) * 256 + t] = 0.f;
    } else {
        g_sum[t] = 0.f; g_sum[t + 256] = 0.f;
        g_sumsq[t] = 0.f; g_sumsq[t + 256] = 0.f;
    }
}
#define SCAN_BLOCKS (BATCH + 48 + 64 + 1)

// ---------------------------------------------------------------------------
// k_compact: self-computed offsets (reduce over g_chunkcnt), valid-row-only
// fp32 -> bf16 copy. Block 0 publishes total/ntiles; ch==0 blocks publish
// per-batch offset/count.
// ---------------------------------------------------------------------------
__global__ void __launch_bounds__(256) k_compact(const float* __restrict__ A,
                                                 const int* __restrict__ mask) {
    __shared__ int red[256];
    __shared__ int sc[256];
    __shared__ short vr[256];
    __shared__ int sh_off, sh_nv;
    const int blk = blockIdx.x, t = threadIdx.x;
    const int srcrow0 = blk * 256;          // == b*SEQ + ch*256 (SEQ = 8*256)

    int cc = g_chunkcnt[t];
    // total across all chunks (block 0 publishes)
    red[t] = cc;
    __syncthreads();
    for (int o = 128; o > 0; o >>= 1) {
        if (t < o) red[t] += red[t + o];
        __syncthreads();
    }
    int total = red[0];
    __syncthreads();
    // this block's destination offset = sum of chunkcnt[0..blk-1]
    red[t] = (t < blk) ? cc : 0;
    __syncthreads();
    for (int o = 128; o > 0; o >>= 1) {
        if (t < o) red[t] += red[t + o];
        __syncthreads();
    }
    if (t == 0) sh_off = red[0];
    __syncthreads();
    const int offset = sh_off;

    if (blk == 0 && t == 0) {
        g_total_i = total;
        g_ntiles_i = (total + 127) >> 7;
    }
    if ((blk & 7) == 0 && t == 0) {
        int b = blk >> 3;
        g_boff[b] = offset;
        int s = 0;
#pragma unroll
        for (int ch = 0; ch < NCHUNK; ch++) s += g_chunkcnt[blk + ch];
        g_cnti[b] = s;
        g_cntf[b] = (float)s;
    }

    // stable local scan of mask -> valid-row list
    int m = mask[srcrow0 + t];
    sc[t] = m;
    __syncthreads();
    for (int o = 1; o < 256; o <<= 1) {
        int v = (t >= o) ? sc[t - o] : 0;
        __syncthreads();
        sc[t] += v;
        __syncthreads();
    }
    if (m) vr[sc[t] - 1] = (short)t;
    if (t == 255) sh_nv = sc[255];
    __syncthreads();
    const int nv = sh_nv;

    // copy only valid rows (reads 50% of A instead of 100%)
    const float4* src = (const float4*)A;
    uint2* dst = (uint2*)g_abf;
    const int NC = DD / 4;   // 192 float4 per row
    for (int i = t; i < nv * NC; i += 256) {
        int vi = i / NC, c = i - vi * NC;
        int sr = srcrow0 + vr[vi];
        float4 v = src[(size_t)sr * NC + c];
        __nv_bfloat162 p0 = __floats2bfloat162_rn(v.x, v.y);
        __nv_bfloat162 p1 = __floats2bfloat162_rn(v.z, v.w);
        dst[(size_t)(offset + vi) * NC + c] = make_uint2(*(uint32_t*)&p0, *(uint32_t*)&p1);
    }
}

// ---------------------------------------------------------------------------
// GEMM1 on compacted rows: bf16 wmma, BK=64, 3-stage cp.async, 2 CTAs/SM.
// Stats epilogue clamps to rows_valid.
// ---------------------------------------------------------------------------
#define BM 128
#define BN 128
#define BK 64
#define STAGES 3
#define A_LD 72
#define B_LD 136
#define A_STG (BM * A_LD)
#define B_STG (BK * B_LD)
#define STG_BF (A_STG + B_STG)
#define SMEM_BYTES (STAGES * STG_BF * 2)   // 107520 B
#define TILE_LD 132

__global__ void __launch_bounds__(256, 2) k_gemm1() {
    if ((int)blockIdx.y >= g_ntiles_i) return;
    extern __shared__ __nv_bfloat16 sm[];

    const int bn = blockIdx.x * BN;
    const int bm = blockIdx.y * BM;
    const int t = threadIdx.x;
    const int warp = t >> 5;
    const int wm = (warp >> 2) * 64;
    const int wn = (warp & 3) * 32;
    const int rows_valid = min(BM, g_total_i - bm);

    wmma::fragment<wmma::accumulator, 16, 16, 16, float> acc[4][2];
#pragma unroll
    for (int i = 0; i < 4; i++)
#pragma unroll
        for (int j = 0; j < 2; j++) wmma::fill_fragment(acc[i][j], 0.f);

    auto prefetch = [&](int it) {
        const int k0 = it * BK;
        __nv_bfloat16* st = sm + (it % STAGES) * STG_BF;
        uint32_t as = smem_u32(st);
        uint32_t bs = smem_u32(st + A_STG);
#pragma unroll
        for (int j = 0; j < 4; j++) {
            int c = j * 256 + t;
            int r = c >> 3, cc = (c & 7) * 8;
            CP_ASYNC16(as + (r * A_LD + cc) * 2,
                       g_abf + (size_t)(bm + r) * DD + k0 + cc);
        }
#pragma unroll
        for (int j = 0; j < 4; j++) {
            int c = j * 256 + t;
            int r = c >> 4, cc = (c & 15) * 8;
            CP_ASYNC16(bs + (r * B_LD + cc) * 2,
                       g_w1bf + (size_t)(k0 + r) * HH + bn + cc);
        }
        CP_COMMIT();
    };

    prefetch(0); prefetch(1);

    const int NIT = DD / BK;   // 12
    for (int it = 0; it < NIT; it++) {
        CP_WAIT(1);
        __syncthreads();
        if (it + 2 < NIT) prefetch(it + 2);
        const __nv_bfloat16* as = sm + (it % STAGES) * STG_BF;
        const __nv_bfloat16* bs = as + A_STG;
#pragma unroll
        for (int kk = 0; kk < BK; kk += 16) {
            wmma::fragment<wmma::matrix_a, 16, 16, 16, __nv_bfloat16, wmma::row_major> fa[4];
            wmma::fragment<wmma::matrix_b, 16, 16, 16, __nv_bfloat16, wmma::row_major> fb[2];
#pragma unroll
            for (int i = 0; i < 4; i++)
                wmma::load_matrix_sync(fa[i], as + (wm + i * 16) * A_LD + kk, A_LD);
#pragma unroll
            for (int j = 0; j < 2; j++)
                wmma::load_matrix_sync(fb[j], bs + kk * B_LD + wn + j * 16, B_LD);
#pragma unroll
            for (int i = 0; i < 4; i++)
#pragma unroll
                for (int j = 0; j < 2; j++)
                    wmma::mma_sync(acc[i][j], fa[i], fb[j], acc[i][j]);
        }
    }
    __syncthreads();

    // ---- Epilogue: fp32 tile (aliases pipe smem), bf16 h store + stats ----
    float* tile = (float*)sm;                 // [128][TILE_LD]
    float* cs = tile + BM * TILE_LD;
    float* cq = cs + BM;

#pragma unroll
    for (int i = 0; i < 4; i++)
#pragma unroll
        for (int j = 0; j < 2; j++)
            wmma::store_matrix_sync(tile + (wm + i * 16) * TILE_LD + wn + j * 16,
                                    acc[i][j], TILE_LD, wmma::mem_row_major);
    __syncthreads();

    __nv_bfloat162* H2 = (__nv_bfloat162*)g_hbf;
#pragma unroll
    for (int i = t; i < BM * 64; i += 256) {
        int r = i >> 6, c2 = (i & 63);
        float x = tile[r * TILE_LD + 2 * c2];
        float y = tile[r * TILE_LD + 2 * c2 + 1];
        H2[((size_t)(bm + r) * HH + bn) / 2 + c2] = __floats2bfloat162_rn(x, y);
    }

    // per-channel sum/sumsq over valid rows only
    int col = t & 127, half = t >> 7;
    float s = 0.f, q = 0.f;
    int rbeg = half * 64;
    int rend = min(rbeg + 64, rows_valid);
    for (int r = rbeg; r < rend; r++) {
        float v = tile[r * TILE_LD + col];
        s += v;
        q += v * v;
    }
    if (half == 0) { cs[col] = s; cq[col] = q; }
    __syncthreads();
    if (half == 1) { cs[col] += s; cq[col] += q; }
    __syncthreads();
    if (t < 128) {
        atomicAdd(&g_sum[bn + t], cs[t]);
        atomicAdd(&g_sumsq[bn + t], cq[t]);
    }
}

// ---------------------------------------------------------------------------
// Pool: bf16x2 vectorized, 64-row chunks (1024 blocks), 8-way MLP.
// Each of 256 threads owns channel pair (2t, 2t+1).
// ---------------------------------------------------------------------------
#define PROWS 64
#define PCH   (SEQ / PROWS)   // 32 chunks per batch
__global__ void __launch_bounds__(256) k_pool(const float* __restrict__ gamma,
                                              const float* __restrict__ beta) {
    int b = blockIdx.x, ch = blockIdx.y, t = threadIdx.x;
    int cnt = g_cnti[b];
    int r0 = ch * PROWS;
    if (r0 >= cnt) return;
    int lim = min(PROWS, cnt - r0);
    int off = g_boff[b];
    int c0 = 2 * t, c1 = 2 * t + 1;

    float n = fmaxf((float)g_total_i, 1.f);
    float mean0 = g_sum[c0] / n, mean1 = g_sum[c1] / n;
    float var0 = g_sumsq[c0] / n - mean0 * mean0;
    float var1 = g_sumsq[c1] / n - mean1 * mean1;
    float rs0 = rsqrtf(fmaxf(var0, 0.f) + EPSF) * gamma[c0];
    float rs1 = rsqrtf(fmaxf(var1, 0.f) + EPSF) * gamma[c1];
    float be0 = beta[c0], be1 = beta[c1];

    const uint32_t* hrow = (const uint32_t*)g_hbf + (size_t)(off + r0) * (HH / 2) + t;
    float s0 = 0.f, s1 = 0.f;
    int l = 0;
    for (; l + 8 <= lim; l += 8) {
        uint32_t w0 = hrow[(size_t)(l + 0) * (HH / 2)];
        uint32_t w1 = hrow[(size_t)(l + 1) * (HH / 2)];
        uint32_t w2 = hrow[(size_t)(l + 2) * (HH / 2)];
        uint32_t w3 = hrow[(size_t)(l + 3) * (HH / 2)];
        uint32_t w4 = hrow[(size_t)(l + 4) * (HH / 2)];
        uint32_t w5 = hrow[(size_t)(l + 5) * (HH / 2)];
        uint32_t w6 = hrow[(size_t)(l + 6) * (HH / 2)];
        uint32_t w7 = hrow[(size_t)(l + 7) * (HH / 2)];
#define POOL_ACC(w) { \
        __nv_bfloat162 v = *(__nv_bfloat162*)&(w); \
        s0 += fmaxf((__bfloat162float(v.x) - mean0) * rs0 + be0, 0.f); \
        s1 += fmaxf((__bfloat162float(v.y) - mean1) * rs1 + be1, 0.f); }
        POOL_ACC(w0) POOL_ACC(w1) POOL_ACC(w2) POOL_ACC(w3)
        POOL_ACC(w4) POOL_ACC(w5) POOL_ACC(w6) POOL_ACC(w7)
    }
    for (; l < lim; l++) {
        uint32_t w = hrow[(size_t)l * (HH / 2)];
        POOL_ACC(w)
    }
#undef POOL_ACC
    atomicAdd(&g_pool[b * HH + c0], s0);
    atomicAdd(&g_pool[b * HH + c1], s1);
}

// ---------------------------------------------------------------------------
// GEMM2: grid (16, 32), 32 k per block, 8-way c-split
// ---------------------------------------------------------------------------
__global__ void __launch_bounds__(256) k_gemm2(const float* __restrict__ W2,
                                               const float* __restrict__ b2,
                                               float* __restrict__ out) {
    __shared__ float ph[HH];
    __shared__ float red[8][32];
    const int b = blockIdx.y, t = threadIdx.x;
    const int kk = t & 31, cg = t >> 5;
    const int k = blockIdx.x * 32 + kk;
    const float inv = 1.f / fmaxf(g_cntf[b], 1.f);
    for (int i = t; i < HH; i += 256) ph[i] = g_pool[b * HH + i] * inv;
    __syncthreads();
    float acc = 0.f;
    const float* w = W2 + (size_t)(cg * 64) * HH + k;
    const float* p = ph + cg * 64;
#pragma unroll 16
    for (int c = 0; c < 64; c++) acc += p[c] * w[(size_t)c * HH];
    red[cg][kk] = acc;
    __syncthreads();
    if (cg == 0) {
        float r = b2[k];
#pragma unroll
        for (int j = 0; j < 8; j++) r += red[j][kk];
        out[b * HH + k] = r;
    }
}

// ---------------------------------------------------------------------------
extern "C" void kernel_launch(void* const* d_in, const int* in_sizes, int n_in,
                              void* d_out, int out_size) {
    const float* hidden = (const float*)d_in[0];
    const int*   mask   = (const int*)d_in[1];
    const float* W1     = (const float*)d_in[2];
    // d_in[3] = b1: cancelled by batch-norm mean subtraction
    const float* gamma  = (const float*)d_in[4];
    const float* beta   = (const float*)d_in[5];
    const float* W2     = (const float*)d_in[6];
    const float* b2     = (const float*)d_in[7];
    float* out = (float*)d_out;

    cudaFuncSetAttribute(k_gemm1, cudaFuncAttributeMaxDynamicSharedMemorySize,
                         SMEM_BYTES);

    k_scan<<<SCAN_BLOCKS, 256>>>(W1, mask);
    k_compact<<<BATCH * NCHUNK, 256>>>(hidden, mask);
    k_gemm1<<<dim3(HH / BN, BL / BM), 256, SMEM_BYTES>>>();
    k_pool<<<dim3(BATCH, PCH), 256>>>(gamma, beta);
    k_gemm2<<<dim3(16, BATCH), 256>>>(W2, b2, out);
}